// round 11
// baseline (speedup 1.0000x reference)
#include <cuda_runtime.h>
#include <math.h>

typedef unsigned long long ull;
typedef unsigned int uint;
#define DV __device__ __forceinline__

// ---------------- scratch (device globals; no allocations) ----------------
__device__ float g_a1[8 * 128 * 256];
__device__ float g_b1[8 * 128 * 256];
__device__ float g_a2[8 * 256 * 256];
__device__ float g_b2[8 * 256 * 256];
__device__ float g_np[8 * 256 * 8];
__device__ float2 g_svi[2][8 * 128 * 256];  // [mode][(b*128+c)*256+k] = {sorted v, idx bits}
__device__ float2 g_uk[2][8 * 128 * 256];   // [mode][(b*128+c)*256+i] = {u, k bits}
__device__ float g_wt[2][32768 * 256];      // transposed W: [mode][k_global][p]
__device__ float g_part[8][16][65536];      // c-split partials (slices 0..1 used)

DV float lrelu(float x) { return x > 0.f ? x : 0.33f * x; }
DV ull ffma2(ull a, ull b, ull c) {
    ull d; asm("fma.rn.f32x2 %0,%1,%2,%3;" : "=l"(d) : "l"(a), "l"(b), "l"(c)); return d;
}
DV ull pack2(float x, float y) {
    ull d; asm("mov.b64 %0,{%1,%2};" : "=l"(d) : "r"(__float_as_uint(x)), "r"(__float_as_uint(y))); return d;
}
DV float2 unpk(ull v) {
    float2 f; asm("mov.b64 {%0,%1},%2;" : "=f"(f.x), "=f"(f.y) : "l"(v)); return f;
}

// ---------------- k1: layer-1 rank terms (8-c tile) ----------------
__global__ void __launch_bounds__(256) k1(const float* __restrict__ x,
                                          const float* __restrict__ w1a, const float* __restrict__ b1a,
                                          const float* __restrict__ w1b, const float* __restrict__ b1b) {
    __shared__ float wa[8][256], wb[8][256];
    int b = blockIdx.x, c0 = blockIdx.y * 8, t = threadIdx.x;
#pragma unroll
    for (int cc = 0; cc < 8; cc++) {
        wa[cc][t] = w1a[(c0 + cc) * 256 + t];
        wb[cc][t] = w1b[(c0 + cc) * 256 + t];
    }
    __syncthreads();
    const float* xb = x + b * 65536;
    float aA[8], aB[8];
#pragma unroll
    for (int cc = 0; cc < 8; cc++) { aA[cc] = 0.f; aB[cc] = 0.f; }
    const float4* xr = (const float4*)(xb + t * 256);
#pragma unroll 4
    for (int j4 = 0; j4 < 64; j4++) {
        float4 v = xr[j4];
#pragma unroll
        for (int cc = 0; cc < 8; cc++)
            aA[cc] += v.x * wa[cc][j4 * 4] + v.y * wa[cc][j4 * 4 + 1] +
                      v.z * wa[cc][j4 * 4 + 2] + v.w * wa[cc][j4 * 4 + 3];
    }
#pragma unroll 4
    for (int i = 0; i < 256; i++) {
        float xv = xb[i * 256 + t];
#pragma unroll
        for (int cc = 0; cc < 8; cc++) aB[cc] += xv * wb[cc][i];
    }
#pragma unroll
    for (int cc = 0; cc < 8; cc++) {
        g_a1[(b * 128 + c0 + cc) * 256 + t] = aA[cc] + b1a[c0 + cc];
        g_b1[(b * 128 + c0 + cc) * 256 + t] = aB[cc] + b1b[c0 + cc];
    }
}

// ---------------- kt: transpose W to [k][p] layout ----------------
__global__ void __launch_bounds__(256) kt(const float* __restrict__ w2a,
                                          const float* __restrict__ w2b) {
    __shared__ float tile[32][33];
    int kb = blockIdx.x * 32, pb = blockIdx.y * 32, mode = blockIdx.z;
    int tx = threadIdx.x & 31, ty = threadIdx.x >> 5;
    const float* W = mode ? w2b : w2a;
    float* wt = g_wt[mode];
#pragma unroll
    for (int r = 0; r < 4; r++)
        tile[ty + 8 * r][tx] = W[(size_t)(pb + ty + 8 * r) * 32768 + kb + tx];
    __syncthreads();
#pragma unroll
    for (int r = 0; r < 4; r++)
        wt[(size_t)(kb + ty + 8 * r) * 256 + pb + tx] = tile[tx][ty + 8 * r];
}

// ---------------- ks: per-(b,c,mode) bitonic sort + thresholds ----------------
__global__ void __launch_bounds__(256) ks() {
    __shared__ float sv[256];
    __shared__ int si[256];
    int b = blockIdx.x, c = blockIdx.y, t = threadIdx.x;
    int mode = blockIdx.z;
    int base = (b * 128 + c) * 256;
    const float* varr = mode ? g_a1 : g_b1;
    const float* uarr = mode ? g_b1 : g_a1;
    sv[t] = varr[base + t];
    si[t] = t;
    __syncthreads();
    for (int k = 2; k <= 256; k <<= 1) {
        for (int j = k >> 1; j > 0; j >>= 1) {
            int ixj = t ^ j;
            if (ixj > t) {
                bool up = ((t & k) == 0);
                float v0 = sv[t], v1 = sv[ixj];
                if ((v0 > v1) == up) {
                    int i0 = si[t], i1 = si[ixj];
                    sv[t] = v1; sv[ixj] = v0;
                    si[t] = i1; si[ixj] = i0;
                }
            }
            __syncthreads();
        }
    }
    g_svi[mode][base + t] = make_float2(sv[t], __int_as_float(si[t]));
    float u = uarr[base + t];
    float nu = -u;
    int lo = 0, hi = 256;
#pragma unroll
    for (int it = 0; it < 8; it++) {
        int mid = (lo + hi) >> 1;
        if (sv[mid] <= nu) lo = mid + 1; else hi = mid;
    }
    g_uk[mode][base + t] = make_float2(u, __int_as_float(lo));
}

// ---------------- kz: zero the e2n accumulator ----------------
__global__ void kz() { g_np[blockIdx.x * 1024 + threadIdx.x] = 0.f; }

// ---------------- k2s: suffix-sum layer-2, transposed-W gather, offset-folded scan ----------------
__global__ void __launch_bounds__(256, 3) k2s() {
    extern __shared__ char smem_raw[];
    float2* SWp = (float2*)smem_raw;        // [257][17] offset-folded suffix pairs
    float2* svis = SWp + 257 * 17;          // [256]
    float2* segtot = svis + 256;            // [16][16]

    int t = threadIdx.x;
    int p0 = blockIdx.x * 16;
    int bm = blockIdx.y, b = bm >> 1, mode = bm & 1;
    int ch = blockIdx.z;                    // c-split half
    int c0 = ch * 64;
    const float2* gsvi = g_svi[mode] + b * 32768;
    const float2* guk = g_uk[mode] + b * 32768;
    const float* wtm = g_wt[mode];

    int p = t & 15, seg = t >> 4;           // scan role: 16 segs x 16 k

    if (t < 16) SWp[256 * 17 + t] = make_float2(0.f, 0.f);   // ki=256 -> empty suffix

    float acc[16];                          // main role: thread = i, acc over 16 p
#pragma unroll
    for (int m = 0; m < 16; m++) acc[m] = 0.f;

    for (int c = c0; c < c0 + 64; c++) {
        __syncthreads();                     // protect SWp/svis from prior main reads
        svis[t] = gsvi[c * 256 + t];
        __syncthreads();
        // pass 1: register sv + gather addresses; local segment totals
        float sv[16];
        int wof[16];
#pragma unroll
        for (int e = 0; e < 16; e++) {
            float2 f2 = svis[seg * 16 + e];
            sv[e] = f2.x;
            wof[e] = (__float_as_int(f2.y) << 8) + p0 + p;   // si*256 + p
        }
        const float* wc = wtm + (size_t)c * 65536;
        float sumw = 0.f, sumv = 0.f;
#pragma unroll
        for (int e = 15; e >= 0; e--) {
            float wv = __ldg(wc + wof[e]);
            sumw += wv;
            sumv = fmaf(wv, sv[e], sumv);
        }
        segtot[seg * 16 + p] = make_float2(sumw, sumv);
        __syncthreads();
        // per-seg offset (suffix over later segments, ascending order)
        float offw = 0.f, offv = 0.f;
        for (int s2 = seg + 1; s2 < 16; s2++) {
            float2 st = segtot[s2 * 16 + p];
            offw += st.x; offv += st.y;
        }
        // pass 2: re-gather (L1-hit), fold offset, store final SWp
        float runw = offw, runv = offv;
#pragma unroll
        for (int e = 15; e >= 0; e--) {
            float wv = __ldg(wc + wof[e]);
            runw += wv;
            runv = fmaf(wv, sv[e], runv);
            SWp[(seg * 16 + e) * 17 + p] = make_float2(runw, runv);
        }
        __syncthreads();
        // main: thread = i
        float2 ukv = __ldg(&guk[c * 256 + t]);
        int ki = __float_as_int(ukv.y);
        const float2* rowK = &SWp[ki * 17];
#pragma unroll
        for (int pp = 0; pp < 16; pp++) {
            float2 s0 = SWp[pp];
            float2 sK = rowK[pp];
            float t0 = fmaf(ukv.x, s0.x, s0.y);
            float t1 = fmaf(ukv.x, sK.x, sK.y);
            acc[pp] = fmaf(0.33f, t0, fmaf(1.0f - 0.33f, t1, acc[pp]));
        }
    }
    // epilogue: coalesced partial writes [p][i]
    float* dst = &g_part[ch][bm][0];
#pragma unroll
    for (int pp = 0; pp < 16; pp++)
        dst[(p0 + pp) * 256 + t] = acc[pp];
}

// ---------------- kr2: deterministic 2-slice reduction + bias ----------------
__global__ void __launch_bounds__(256) kr2(const float* __restrict__ b2a,
                                           const float* __restrict__ b2b) {
    int idx = (blockIdx.x * 256 + threadIdx.x) * 4;
    int bm = idx >> 16, rem = idx & 65535;
    int p = rem >> 8;
    float4 s = *(const float4*)&g_part[0][bm][rem];
    float4 u = *(const float4*)&g_part[1][bm][rem];
    s.x += u.x; s.y += u.y; s.z += u.z; s.w += u.w;
    float bias = (bm & 1) ? b2b[p] : b2a[p];
    s.x += bias; s.y += bias; s.z += bias; s.w += bias;
    float* out = ((bm & 1) ? g_b2 : g_a2) + (bm >> 1) * 65536 + rem;
    *(float4*)out = s;
}

// ---------------- k3: e2n contraction ----------------
__global__ void __launch_bounds__(256) k3(const float* __restrict__ ew) {
    __shared__ float Bsm[256];
    __shared__ ull Esm[256 * 4];
    int b = blockIdx.x, pc = blockIdx.y, tid = threadIdx.x;
    ull a4[4] = {0ULL, 0ULL, 0ULL, 0ULL};
    for (int p = pc * 4; p < pc * 4 + 4; p++) {
        __syncthreads();
        Bsm[tid] = g_b2[(b * 256 + p) * 256 + tid];
        float e[8];
#pragma unroll
        for (int q = 0; q < 8; q++) e[q] = ew[q * 65536 + p * 256 + tid];
#pragma unroll
        for (int q = 0; q < 4; q++) Esm[tid * 4 + q] = pack2(e[2 * q], e[2 * q + 1]);
        __syncthreads();
        float ai = g_a2[(b * 256 + p) * 256 + tid];
#pragma unroll 4
        for (int j = 0; j < 256; j++) {
            float t = lrelu(ai + Bsm[j]);
            ull ts = pack2(t, t);
            const ull* er = &Esm[j * 4];
            a4[0] = ffma2(er[0], ts, a4[0]);
            a4[1] = ffma2(er[1], ts, a4[1]);
            a4[2] = ffma2(er[2], ts, a4[2]);
            a4[3] = ffma2(er[3], ts, a4[3]);
        }
    }
    float* dst = &g_np[b * 2048 + tid * 8];
#pragma unroll
    for (int q = 0; q < 4; q++) {
        float2 f = unpk(a4[q]);
        atomicAdd(dst + 2 * q, f.x);
        atomicAdd(dst + 2 * q + 1, f.y);
    }
}

// ---------------- k4: GCN / pooling / readout / MLP tail ----------------
__global__ void __launch_bounds__(256) k4(const float* __restrict__ x, const float* __restrict__ e2n_b,
    const float* __restrict__ a11_w, const float* __restrict__ a11_b,
    const float* __restrict__ a12_w, const float* __restrict__ a12_b,
    const float* __restrict__ g1_w,  const float* __restrict__ g1_b,
    const float* __restrict__ a21_w, const float* __restrict__ a21_b,
    const float* __restrict__ a22_w, const float* __restrict__ a22_b,
    const float* __restrict__ d1_w,  const float* __restrict__ d1_b,
    const float* __restrict__ d2_w,  const float* __restrict__ d2_b,
    const float* __restrict__ d3_w,  const float* __restrict__ d3_b,
    float* __restrict__ out) {
    __shared__ uint  m0[256][8];
    __shared__ float nod[256][8];
    __shared__ float dg0[256];
    __shared__ float tp[256];
    __shared__ float sc[256];
    __shared__ float t8[256][8];
    __shared__ int   sel[128];
    __shared__ float hg[128][8];
    __shared__ float on[128][8];
    __shared__ uint  m1[128][4];
    __shared__ float dg1[128];
    __shared__ float z[16];
    __shared__ float z1[128];
    __shared__ float z2[64];

    int b = blockIdx.x, t = threadIdx.x;
    const float* xb = x + b * 65536;
    {
        int w = t >> 5, l = t & 31;
        for (int r = 0; r < 32; r++) {
            int i = w * 32 + r;
            int d = 0;
#pragma unroll
            for (int w8 = 0; w8 < 8; w8++) {
                float xv = xb[i * 256 + w8 * 32 + l];
                uint u = __ballot_sync(0xffffffffu, xv > 0.f);
                if (l == 0) { m0[i][w8] = u; d += __popc(u); }
            }
            if (l == 0) dg0[i] = (float)d;
        }
#pragma unroll
        for (int f = 0; f < 8; f++) nod[t][f] = lrelu(g_np[b * 2048 + t * 8 + f] + e2n_b[f]);
    }
    __syncthreads();
    {
        float s = 0;
#pragma unroll
        for (int f = 0; f < 8; f++) s += nod[t][f] * a11_w[f];
        tp[t] = s / dg0[t];
    }
    __syncthreads();
    {
        float s = 0;
        for (int j = 0; j < 256; j++) if ((m0[t][j >> 5] >> (j & 31)) & 1) s += tp[j];
        sc[t] = lrelu(s + a11_b[0]);
    }
    __syncthreads();
    tp[t] = sc[t] * a12_w[0] / dg0[t];
    __syncthreads();
    {
        float s = 0;
        for (int j = 0; j < 256; j++) if ((m0[t][j >> 5] >> (j & 31)) & 1) s += tp[j];
        sc[t] = 1.f / (1.f + expf(-(s + a12_b[0])));
    }
    __syncthreads();
    {
        float my = sc[t]; int r = 0;
        for (int j = 0; j < 256; j++) {
            float vj = sc[j];
            r += (vj > my) || (vj == my && j < t);
        }
        if (r < 128) sel[r] = t;
    }
    __syncthreads();
    for (int idx = t; idx < 1024; idx += 256) {
        int r = idx >> 3, f = idx & 7; int i = sel[r];
        on[r][f] = nod[i][f] * (1.f + sc[i]);
    }
    if (t < 128) {
        int i = sel[t], d = 0;
#pragma unroll
        for (int w = 0; w < 4; w++) {
            uint u = 0;
            for (int l = 0; l < 32; l++) {
                int j = sel[w * 32 + l];
                u |= ((m0[i][j >> 5] >> (j & 31)) & 1u) << l;
            }
            m1[t][w] = u; d += __popc(u);
        }
        dg1[t] = (float)d;
    }
    __syncthreads();
    if (t < 8) {
        float mx = -1e30f, sm = 0;
        for (int r = 0; r < 128; r++) { float v = on[r][t]; mx = fmaxf(mx, v); sm += v; }
        z[t] = mx; z[8 + t] = sm * (1.f / 128.f);
    }
    __syncthreads();
    for (int idx = t; idx < 1024; idx += 256) {
        int r2 = idx >> 3, fo = idx & 7;
        float s = 0;
#pragma unroll
        for (int f = 0; f < 8; f++) s += on[r2][f] * g1_w[fo * 8 + f];
        t8[r2][fo] = s / dg1[r2];
    }
    __syncthreads();
    for (int idx = t; idx < 1024; idx += 256) {
        int r = idx >> 3, fo = idx & 7;
        float s = 0;
        for (int j = 0; j < 128; j++) if ((m1[r][j >> 5] >> (j & 31)) & 1) s += t8[j][fo];
        hg[r][fo] = s + g1_b[fo];
    }
    __syncthreads();
    if (t < 128) {
        float s = 0;
#pragma unroll
        for (int f = 0; f < 8; f++) s += hg[t][f] * a21_w[f];
        tp[t] = s / dg1[t];
    }
    __syncthreads();
    if (t < 128) {
        float s = 0;
        for (int j = 0; j < 128; j++) if ((m1[t][j >> 5] >> (j & 31)) & 1) s += tp[j];
        sc[t] = lrelu(s + a21_b[0]);
    }
    __syncthreads();
    if (t < 128) tp[t] = sc[t] * a22_w[0] / dg1[t];
    __syncthreads();
    if (t < 128) {
        float s = 0;
        for (int j = 0; j < 128; j++) if ((m1[t][j >> 5] >> (j & 31)) & 1) s += tp[j];
        sc[t] = 1.f / (1.f + expf(-(s + a22_b[0])));
    }
    __syncthreads();
    if (t < 128) {
        float my = sc[t]; int r = 0;
        for (int j = 0; j < 128; j++) {
            float vj = sc[j];
            r += (vj > my) || (vj == my && j < t);
        }
        if (r < 64) sel[r] = t;
    }
    __syncthreads();
    for (int idx = t; idx < 512; idx += 256) {
        int r = idx >> 3, f = idx & 7; int i = sel[r];
        on[r][f] = hg[i][f] * (1.f + sc[i]);
    }
    __syncthreads();
    if (t < 8) {
        float mx = -1e30f, sm = 0;
        for (int r = 0; r < 64; r++) { float v = on[r][t]; mx = fmaxf(mx, v); sm += v; }
        z[t] += mx; z[8 + t] += sm * (1.f / 64.f);
    }
    __syncthreads();
    if (t < 128) {
        float s = d1_b[t];
#pragma unroll
        for (int f = 0; f < 16; f++) s += z[f] * d1_w[t * 16 + f];
        z1[t] = lrelu(s);
    }
    __syncthreads();
    if (t < 64) {
        float s = d2_b[t];
        for (int f = 0; f < 128; f++) s += z1[f] * d2_w[t * 128 + f];
        z2[t] = lrelu(s);
    }
    __syncthreads();
    if (t == 0) {
        float s = d3_b[0];
        for (int f = 0; f < 64; f++) s += z2[f] * d3_w[f];
        out[b] = s;
    }
}

// ---------------- launcher ----------------
extern "C" void kernel_launch(void* const* d_in, const int* in_sizes, int n_in,
                              void* d_out, int out_size) {
    const float* x    = (const float*)d_in[0];
    const float* w1a  = (const float*)d_in[1];
    const float* b1a  = (const float*)d_in[2];
    const float* w1b  = (const float*)d_in[3];
    const float* b1b  = (const float*)d_in[4];
    const float* w2a  = (const float*)d_in[5];
    const float* b2a  = (const float*)d_in[6];
    const float* w2b  = (const float*)d_in[7];
    const float* b2b  = (const float*)d_in[8];
    const float* e2nw = (const float*)d_in[9];
    const float* e2nb = (const float*)d_in[10];
    const float* a11w = (const float*)d_in[11];
    const float* a11b = (const float*)d_in[12];
    const float* a12w = (const float*)d_in[13];
    const float* a12b = (const float*)d_in[14];
    const float* g1w  = (const float*)d_in[15];
    const float* g1b  = (const float*)d_in[16];
    const float* a21w = (const float*)d_in[17];
    const float* a21b = (const float*)d_in[18];
    const float* a22w = (const float*)d_in[19];
    const float* a22b = (const float*)d_in[20];
    const float* d1w  = (const float*)d_in[21];
    const float* d1b  = (const float*)d_in[22];
    const float* d2w  = (const float*)d_in[23];
    const float* d2b  = (const float*)d_in[24];
    const float* d3w  = (const float*)d_in[25];
    const float* d3b  = (const float*)d_in[26];

    // k2s smem: SWp 257*17*8 + svis 2048 + segtot 2048 = 38,984 B
    const int k2s_smem = 257 * 17 * 8 + 2048 + 2048;
    cudaFuncSetAttribute(k2s, cudaFuncAttributeMaxDynamicSharedMemorySize, k2s_smem);

    k1<<<dim3(8, 16), 256>>>(x, w1a, b1a, w1b, b1b);
    kt<<<dim3(1024, 8, 2), 256>>>(w2a, w2b);
    ks<<<dim3(8, 128, 2), 256>>>();
    kz<<<16, 1024>>>();
    k2s<<<dim3(16, 16, 2), 256, k2s_smem>>>();
    kr2<<<1024, 256>>>(b2a, b2b);
    k3<<<dim3(8, 64), 256>>>(e2nw);
    k4<<<8, 256>>>(x, e2nb, a11w, a11b, a12w, a12b, g1w, g1b, a21w, a21b,
                   a22w, a22b, d1w, d1b, d2w, d2b, d3w, d3b, (float*)d_out);
}

// round 12
// speedup vs baseline: 1.2093x; 1.2093x over previous
#include <cuda_runtime.h>
#include <math.h>

typedef unsigned long long ull;
typedef unsigned int uint;
#define DV __device__ __forceinline__

// ---------------- scratch (device globals; no allocations) ----------------
__device__ float g_a1[8 * 128 * 256];
__device__ float g_b1[8 * 128 * 256];
__device__ float g_a2[8 * 256 * 256];
__device__ float g_b2[8 * 256 * 256];
__device__ float g_np[8 * 256 * 8];
__device__ float2 g_svi[2][8 * 128 * 256];  // [mode][(b*128+c)*256+k] = {sorted v, idx bits}
__device__ float2 g_uk[2][8 * 128 * 256];   // [mode][(b*128+c)*256+i] = {u, k bits}
__device__ float g_part[2][16][65536];      // c-split partials

DV float lrelu(float x) { return x > 0.f ? x : 0.33f * x; }
DV ull ffma2(ull a, ull b, ull c) {
    ull d; asm("fma.rn.f32x2 %0,%1,%2,%3;" : "=l"(d) : "l"(a), "l"(b), "l"(c)); return d;
}
DV ull pack2(float x, float y) {
    ull d; asm("mov.b64 %0,{%1,%2};" : "=l"(d) : "r"(__float_as_uint(x)), "r"(__float_as_uint(y))); return d;
}
DV float2 unpk(ull v) {
    float2 f; asm("mov.b64 {%0,%1},%2;" : "=f"(f.x), "=f"(f.y) : "l"(v)); return f;
}

// ---------------- k1: layer-1 rank terms (8-c tile: x traffic /8) ----------------
__global__ void __launch_bounds__(256) k1(const float* __restrict__ x,
                                          const float* __restrict__ w1a, const float* __restrict__ b1a,
                                          const float* __restrict__ w1b, const float* __restrict__ b1b) {
    __shared__ float wa[8][256], wb[8][256];
    int b = blockIdx.x, c0 = blockIdx.y * 8, t = threadIdx.x;
#pragma unroll
    for (int cc = 0; cc < 8; cc++) {
        wa[cc][t] = w1a[(c0 + cc) * 256 + t];
        wb[cc][t] = w1b[(c0 + cc) * 256 + t];
    }
    __syncthreads();
    const float* xb = x + b * 65536;
    float aA[8], aB[8];
#pragma unroll
    for (int cc = 0; cc < 8; cc++) { aA[cc] = 0.f; aB[cc] = 0.f; }
    const float4* xr = (const float4*)(xb + t * 256);
#pragma unroll 4
    for (int j4 = 0; j4 < 64; j4++) {
        float4 v = xr[j4];
#pragma unroll
        for (int cc = 0; cc < 8; cc++)
            aA[cc] += v.x * wa[cc][j4 * 4] + v.y * wa[cc][j4 * 4 + 1] +
                      v.z * wa[cc][j4 * 4 + 2] + v.w * wa[cc][j4 * 4 + 3];
    }
#pragma unroll 4
    for (int i = 0; i < 256; i++) {
        float xv = xb[i * 256 + t];
#pragma unroll
        for (int cc = 0; cc < 8; cc++) aB[cc] += xv * wb[cc][i];
    }
#pragma unroll
    for (int cc = 0; cc < 8; cc++) {
        g_a1[(b * 128 + c0 + cc) * 256 + t] = aA[cc] + b1a[c0 + cc];
        g_b1[(b * 128 + c0 + cc) * 256 + t] = aB[cc] + b1b[c0 + cc];
    }
}

// ---------------- ks: per-(b,c,mode) bitonic sort + thresholds ----------------
__global__ void __launch_bounds__(256) ks() {
    __shared__ float sv[256];
    __shared__ int si[256];
    int b = blockIdx.x, c = blockIdx.y, t = threadIdx.x;
    int mode = blockIdx.z;
    int base = (b * 128 + c) * 256;
    const float* varr = mode ? g_a1 : g_b1;
    const float* uarr = mode ? g_b1 : g_a1;
    sv[t] = varr[base + t];
    si[t] = t;
    __syncthreads();
    for (int k = 2; k <= 256; k <<= 1) {
        for (int j = k >> 1; j > 0; j >>= 1) {
            int ixj = t ^ j;
            if (ixj > t) {
                bool up = ((t & k) == 0);
                float v0 = sv[t], v1 = sv[ixj];
                if ((v0 > v1) == up) {
                    int i0 = si[t], i1 = si[ixj];
                    sv[t] = v1; sv[ixj] = v0;
                    si[t] = i1; si[ixj] = i0;
                }
            }
            __syncthreads();
        }
    }
    g_svi[mode][base + t] = make_float2(sv[t], __int_as_float(si[t]));
    float u = uarr[base + t];
    float nu = -u;
    int lo = 0, hi = 256;
#pragma unroll
    for (int it = 0; it < 8; it++) {
        int mid = (lo + hi) >> 1;
        if (sv[mid] <= nu) lo = mid + 1; else hi = mid;
    }
    g_uk[mode][base + t] = make_float2(u, __int_as_float(lo));
}

// ---------------- kz: zero the e2n accumulator ----------------
__global__ void kz() { g_np[blockIdx.x * 1024 + threadIdx.x] = 0.f; }

// ---------------- k2s: layer-2 via sorted suffix sums (16-p tiles, 16x16 segs, c-split x2) ----------------
__global__ void __launch_bounds__(256, 3) k2s(const float* __restrict__ w2a,
                                              const float* __restrict__ w2b) {
    extern __shared__ char smem_raw[];
    float2* SWp = (float2*)smem_raw;        // [257][17] raw suffix pairs
    float2* svi = SWp + 257 * 17;           // [256]
    float2* uk = svi + 256;                 // [256]
    float2* segtot = uk + 256;              // [16][16]
    float2* OS = segtot + 16 * 16;          // [17][16] per-seg offsets (row 16 = zeros)
    float* wtmp = (float*)(OS + 17 * 16);   // [256][17]

    int t = threadIdx.x;
    int p0 = blockIdx.x * 16;
    int bm = blockIdx.y, b = bm >> 1, mode = bm & 1;
    int ch = blockIdx.z;                    // c-split half
    int c0 = ch * 64;
    const float* W = mode ? w2b : w2a;
    const float2* gsvi = g_svi[mode] + b * 32768;
    const float2* guk = g_uk[mode] + b * 32768;

    int p = t & 15, seg = t >> 4;       // 16 segs x 16 k
    int wlp = t >> 4, wls = t & 15;     // W loader: 16 p rows x 16 k-groups

    if (t < 16) {
        SWp[256 * 17 + t] = make_float2(0.f, 0.f);   // k=256 empty suffix
        OS[16 * 16 + t] = make_float2(0.f, 0.f);     // offset row for ki=256
    }

    float acc[16];
#pragma unroll
    for (int m = 0; m < 16; m++) acc[m] = 0.f;

    const float* wbase = W + (size_t)(p0 + wlp) * 32768;

    for (int c = c0; c < c0 + 64; c++) {
        __syncthreads();
        svi[t] = gsvi[c * 256 + t];
        uk[t] = guk[c * 256 + t];
        const float* wrow = wbase + c * 256;
#pragma unroll
        for (int m = 0; m < 4; m++) {
            float4 f = *(const float4*)(wrow + m * 64 + wls * 4);
            int kb = m * 64 + wls * 4;
            wtmp[(kb + 0) * 17 + wlp] = f.x;
            wtmp[(kb + 1) * 17 + wlp] = f.y;
            wtmp[(kb + 2) * 17 + wlp] = f.z;
            wtmp[(kb + 3) * 17 + wlp] = f.w;
        }
        __syncthreads();
        // backward suffix scan in this thread's 16-k segment (reg-batched 8+8)
        float run = 0.f, runv = 0.f;
#pragma unroll
        for (int batch = 1; batch >= 0; batch--) {
            float2 sv8[8];
            float wv8[8];
#pragma unroll
            for (int e = 7; e >= 0; e--) sv8[e] = svi[seg * 16 + batch * 8 + e];
#pragma unroll
            for (int e = 7; e >= 0; e--) wv8[e] = wtmp[__float_as_int(sv8[e].y) * 17 + p];
#pragma unroll
            for (int e = 7; e >= 0; e--) {
                int kk = seg * 16 + batch * 8 + e;
                run += wv8[e];
                runv = fmaf(wv8[e], sv8[e].x, runv);
                SWp[kk * 17 + p] = make_float2(run, runv);
            }
        }
        segtot[seg * 16 + p] = make_float2(run, runv);
        __syncthreads();
        {
            float offw = 0.f, offv = 0.f;
            for (int s2 = seg + 1; s2 < 16; s2++) {
                float2 st = segtot[s2 * 16 + p];
                offw += st.x; offv += st.y;
            }
            OS[seg * 16 + p] = make_float2(offw, offv);
        }
        __syncthreads();
        float2 sw0r = SWp[p];
        float2 os0 = OS[p];
        float sw0x = sw0r.x + os0.x, sw0y = sw0r.y + os0.y;
#pragma unroll 4
        for (int m = 0; m < 16; m++) {
            int i = seg * 16 + m;
            float2 ukv = uk[i];
            int ki = __float_as_int(ukv.y);
            float2 s2 = SWp[ki * 17 + p];
            float2 os = OS[(ki >> 4) * 16 + p];
            float t1 = fmaf(ukv.x, s2.x + os.x, s2.y + os.y);
            float t0 = fmaf(ukv.x, sw0x, sw0y);
            acc[m] = fmaf(0.33f, t0, fmaf(1.0f - 0.33f, t1, acc[m]));
        }
    }
    // epilogue: partial writes (no bias; reduced in kr2)
    float* dst = &g_part[ch][bm][0] + (size_t)(p0 + p) * 256 + seg * 16;
#pragma unroll
    for (int m = 0; m < 16; m += 4) {
        float4 o = make_float4(acc[m], acc[m + 1], acc[m + 2], acc[m + 3]);
        *(float4*)(dst + m) = o;
    }
}

// ---------------- kr2: deterministic 2-slice reduction + bias ----------------
__global__ void __launch_bounds__(256) kr2(const float* __restrict__ b2a,
                                           const float* __restrict__ b2b) {
    int idx = (blockIdx.x * 256 + threadIdx.x) * 4;
    int bm = idx >> 16, rem = idx & 65535;
    int p = rem >> 8;
    float4 s = *(const float4*)&g_part[0][bm][rem];
    float4 u = *(const float4*)&g_part[1][bm][rem];
    s.x += u.x; s.y += u.y; s.z += u.z; s.w += u.w;
    float bias = (bm & 1) ? b2b[p] : b2a[p];
    s.x += bias; s.y += bias; s.z += bias; s.w += bias;
    float* out = ((bm & 1) ? g_b2 : g_a2) + (bm >> 1) * 65536 + rem;
    *(float4*)out = s;
}

// ---------------- k3: e2n contraction ----------------
__global__ void __launch_bounds__(256) k3(const float* __restrict__ ew) {
    __shared__ float Bsm[256];
    __shared__ ull Esm[256 * 4];
    int b = blockIdx.x, pc = blockIdx.y, tid = threadIdx.x;
    ull a4[4] = {0ULL, 0ULL, 0ULL, 0ULL};
    for (int p = pc * 4; p < pc * 4 + 4; p++) {
        __syncthreads();
        Bsm[tid] = g_b2[(b * 256 + p) * 256 + tid];
        float e[8];
#pragma unroll
        for (int q = 0; q < 8; q++) e[q] = ew[q * 65536 + p * 256 + tid];
#pragma unroll
        for (int q = 0; q < 4; q++) Esm[tid * 4 + q] = pack2(e[2 * q], e[2 * q + 1]);
        __syncthreads();
        float ai = g_a2[(b * 256 + p) * 256 + tid];
#pragma unroll 4
        for (int j = 0; j < 256; j++) {
            float t = lrelu(ai + Bsm[j]);
            ull ts = pack2(t, t);
            const ull* er = &Esm[j * 4];
            a4[0] = ffma2(er[0], ts, a4[0]);
            a4[1] = ffma2(er[1], ts, a4[1]);
            a4[2] = ffma2(er[2], ts, a4[2]);
            a4[3] = ffma2(er[3], ts, a4[3]);
        }
    }
    float* dst = &g_np[b * 2048 + tid * 8];
#pragma unroll
    for (int q = 0; q < 4; q++) {
        float2 f = unpk(a4[q]);
        atomicAdd(dst + 2 * q, f.x);
        atomicAdd(dst + 2 * q + 1, f.y);
    }
}

// ---------------- k4: GCN / pooling / readout / MLP tail ----------------
__global__ void __launch_bounds__(256) k4(const float* __restrict__ x, const float* __restrict__ e2n_b,
    const float* __restrict__ a11_w, const float* __restrict__ a11_b,
    const float* __restrict__ a12_w, const float* __restrict__ a12_b,
    const float* __restrict__ g1_w,  const float* __restrict__ g1_b,
    const float* __restrict__ a21_w, const float* __restrict__ a21_b,
    const float* __restrict__ a22_w, const float* __restrict__ a22_b,
    const float* __restrict__ d1_w,  const float* __restrict__ d1_b,
    const float* __restrict__ d2_w,  const float* __restrict__ d2_b,
    const float* __restrict__ d3_w,  const float* __restrict__ d3_b,
    float* __restrict__ out) {
    __shared__ uint  m0[256][8];
    __shared__ float nod[256][8];
    __shared__ float dg0[256];
    __shared__ float tp[256];
    __shared__ float sc[256];
    __shared__ float t8[256][8];
    __shared__ int   sel[128];
    __shared__ float hg[128][8];
    __shared__ float on[128][8];
    __shared__ uint  m1[128][4];
    __shared__ float dg1[128];
    __shared__ float z[16];
    __shared__ float z1[128];
    __shared__ float z2[64];

    int b = blockIdx.x, t = threadIdx.x;
    const float* xb = x + b * 65536;
    {
        int w = t >> 5, l = t & 31;
        for (int r = 0; r < 32; r++) {
            int i = w * 32 + r;
            int d = 0;
#pragma unroll
            for (int w8 = 0; w8 < 8; w8++) {
                float xv = xb[i * 256 + w8 * 32 + l];
                uint u = __ballot_sync(0xffffffffu, xv > 0.f);
                if (l == 0) { m0[i][w8] = u; d += __popc(u); }
            }
            if (l == 0) dg0[i] = (float)d;
        }
#pragma unroll
        for (int f = 0; f < 8; f++) nod[t][f] = lrelu(g_np[b * 2048 + t * 8 + f] + e2n_b[f]);
    }
    __syncthreads();
    {
        float s = 0;
#pragma unroll
        for (int f = 0; f < 8; f++) s += nod[t][f] * a11_w[f];
        tp[t] = s / dg0[t];
    }
    __syncthreads();
    {
        float s = 0;
        for (int j = 0; j < 256; j++) if ((m0[t][j >> 5] >> (j & 31)) & 1) s += tp[j];
        sc[t] = lrelu(s + a11_b[0]);
    }
    __syncthreads();
    tp[t] = sc[t] * a12_w[0] / dg0[t];
    __syncthreads();
    {
        float s = 0;
        for (int j = 0; j < 256; j++) if ((m0[t][j >> 5] >> (j & 31)) & 1) s += tp[j];
        sc[t] = 1.f / (1.f + expf(-(s + a12_b[0])));
    }
    __syncthreads();
    {
        float my = sc[t]; int r = 0;
        for (int j = 0; j < 256; j++) {
            float vj = sc[j];
            r += (vj > my) || (vj == my && j < t);
        }
        if (r < 128) sel[r] = t;
    }
    __syncthreads();
    for (int idx = t; idx < 1024; idx += 256) {
        int r = idx >> 3, f = idx & 7; int i = sel[r];
        on[r][f] = nod[i][f] * (1.f + sc[i]);
    }
    if (t < 128) {
        int i = sel[t], d = 0;
#pragma unroll
        for (int w = 0; w < 4; w++) {
            uint u = 0;
            for (int l = 0; l < 32; l++) {
                int j = sel[w * 32 + l];
                u |= ((m0[i][j >> 5] >> (j & 31)) & 1u) << l;
            }
            m1[t][w] = u; d += __popc(u);
        }
        dg1[t] = (float)d;
    }
    __syncthreads();
    if (t < 8) {
        float mx = -1e30f, sm = 0;
        for (int r = 0; r < 128; r++) { float v = on[r][t]; mx = fmaxf(mx, v); sm += v; }
        z[t] = mx; z[8 + t] = sm * (1.f / 128.f);
    }
    __syncthreads();
    for (int idx = t; idx < 1024; idx += 256) {
        int r2 = idx >> 3, fo = idx & 7;
        float s = 0;
#pragma unroll
        for (int f = 0; f < 8; f++) s += on[r2][f] * g1_w[fo * 8 + f];
        t8[r2][fo] = s / dg1[r2];
    }
    __syncthreads();
    for (int idx = t; idx < 1024; idx += 256) {
        int r = idx >> 3, fo = idx & 7;
        float s = 0;
        for (int j = 0; j < 128; j++) if ((m1[r][j >> 5] >> (j & 31)) & 1) s += t8[j][fo];
        hg[r][fo] = s + g1_b[fo];
    }
    __syncthreads();
    if (t < 128) {
        float s = 0;
#pragma unroll
        for (int f = 0; f < 8; f++) s += hg[t][f] * a21_w[f];
        tp[t] = s / dg1[t];
    }
    __syncthreads();
    if (t < 128) {
        float s = 0;
        for (int j = 0; j < 128; j++) if ((m1[t][j >> 5] >> (j & 31)) & 1) s += tp[j];
        sc[t] = lrelu(s + a21_b[0]);
    }
    __syncthreads();
    if (t < 128) tp[t] = sc[t] * a22_w[0] / dg1[t];
    __syncthreads();
    if (t < 128) {
        float s = 0;
        for (int j = 0; j < 128; j++) if ((m1[t][j >> 5] >> (j & 31)) & 1) s += tp[j];
        sc[t] = 1.f / (1.f + expf(-(s + a22_b[0])));
    }
    __syncthreads();
    if (t < 128) {
        float my = sc[t]; int r = 0;
        for (int j = 0; j < 128; j++) {
            float vj = sc[j];
            r += (vj > my) || (vj == my && j < t);
        }
        if (r < 64) sel[r] = t;
    }
    __syncthreads();
    for (int idx = t; idx < 512; idx += 256) {
        int r = idx >> 3, f = idx & 7; int i = sel[r];
        on[r][f] = hg[i][f] * (1.f + sc[i]);
    }
    __syncthreads();
    if (t < 8) {
        float mx = -1e30f, sm = 0;
        for (int r = 0; r < 64; r++) { float v = on[r][t]; mx = fmaxf(mx, v); sm += v; }
        z[t] += mx; z[8 + t] += sm * (1.f / 64.f);
    }
    __syncthreads();
    if (t < 128) {
        float s = d1_b[t];
#pragma unroll
        for (int f = 0; f < 16; f++) s += z[f] * d1_w[t * 16 + f];
        z1[t] = lrelu(s);
    }
    __syncthreads();
    if (t < 64) {
        float s = d2_b[t];
        for (int f = 0; f < 128; f++) s += z1[f] * d2_w[t * 128 + f];
        z2[t] = lrelu(s);
    }
    __syncthreads();
    if (t == 0) {
        float s = d3_b[0];
        for (int f = 0; f < 64; f++) s += z2[f] * d3_w[f];
        out[b] = s;
    }
}

// ---------------- launcher ----------------
extern "C" void kernel_launch(void* const* d_in, const int* in_sizes, int n_in,
                              void* d_out, int out_size) {
    const float* x    = (const float*)d_in[0];
    const float* w1a  = (const float*)d_in[1];
    const float* b1a  = (const float*)d_in[2];
    const float* w1b  = (const float*)d_in[3];
    const float* b1b  = (const float*)d_in[4];
    const float* w2a  = (const float*)d_in[5];
    const float* b2a  = (const float*)d_in[6];
    const float* w2b  = (const float*)d_in[7];
    const float* b2b  = (const float*)d_in[8];
    const float* e2nw = (const float*)d_in[9];
    const float* e2nb = (const float*)d_in[10];
    const float* a11w = (const float*)d_in[11];
    const float* a11b = (const float*)d_in[12];
    const float* a12w = (const float*)d_in[13];
    const float* a12b = (const float*)d_in[14];
    const float* g1w  = (const float*)d_in[15];
    const float* g1b  = (const float*)d_in[16];
    const float* a21w = (const float*)d_in[17];
    const float* a21b = (const float*)d_in[18];
    const float* a22w = (const float*)d_in[19];
    const float* a22b = (const float*)d_in[20];
    const float* d1w  = (const float*)d_in[21];
    const float* d1b  = (const float*)d_in[22];
    const float* d2w  = (const float*)d_in[23];
    const float* d2b  = (const float*)d_in[24];
    const float* d3w  = (const float*)d_in[25];
    const float* d3b  = (const float*)d_in[26];

    // k2s smem: SWp 257*17*8 + svi 2048 + uk 2048 + segtot 2048 + OS 2176 + wtmp 256*17*4
    const int k2s_smem = 257 * 17 * 8 + 2048 + 2048 + 2048 + 2176 + 256 * 17 * 4;  // 60,680 B
    cudaFuncSetAttribute(k2s, cudaFuncAttributeMaxDynamicSharedMemorySize, k2s_smem);

    k1<<<dim3(8, 16), 256>>>(x, w1a, b1a, w1b, b1b);
    ks<<<dim3(8, 128, 2), 256>>>();
    kz<<<16, 1024>>>();
    k2s<<<dim3(16, 16, 2), 256, k2s_smem>>>(w2a, w2b);
    kr2<<<1024, 256>>>(b2a, b2b);
    k3<<<dim3(8, 64), 256>>>(e2nw);
    k4<<<8, 256>>>(x, e2nb, a11w, a11b, a12w, a12b, g1w, g1b, a21w, a21b,
                   a22w, a22b, d1w, d1b, d2w, d2b, d3w, d3b, (float*)d_out);
}

// round 14
// speedup vs baseline: 1.3048x; 1.0790x over previous
#include <cuda_runtime.h>
#include <math.h>

typedef unsigned long long ull;
typedef unsigned int uint;
#define DV __device__ __forceinline__

// ---------------- scratch (device globals; no allocations) ----------------
__device__ float g_a1[8 * 128 * 256];
__device__ float g_b1[8 * 128 * 256];
__device__ float g_a2[8 * 256 * 256];
__device__ float g_b2[8 * 256 * 256];
__device__ float g_np[8 * 256 * 8];
__device__ float2 g_svi[2][8 * 128 * 256];  // [mode][(b*128+c)*256+k] = {sorted v, idx bits}
__device__ float2 g_uk[2][8 * 128 * 256];   // [mode][(b*128+c)*256+i] = {u, k bits}

DV float lrelu(float x) { return x > 0.f ? x : 0.33f * x; }
DV ull ffma2(ull a, ull b, ull c) {
    ull d; asm("fma.rn.f32x2 %0,%1,%2,%3;" : "=l"(d) : "l"(a), "l"(b), "l"(c)); return d;
}
DV ull pack2(float x, float y) {
    ull d; asm("mov.b64 %0,{%1,%2};" : "=l"(d) : "r"(__float_as_uint(x)), "r"(__float_as_uint(y))); return d;
}
DV float2 unpk(ull v) {
    float2 f; asm("mov.b64 {%0,%1},%2;" : "=f"(f.x), "=f"(f.y) : "l"(v)); return f;
}

// ---------------- k1: layer-1 rank terms (8-c tile) ----------------
__global__ void __launch_bounds__(256) k1(const float* __restrict__ x,
                                          const float* __restrict__ w1a, const float* __restrict__ b1a,
                                          const float* __restrict__ w1b, const float* __restrict__ b1b) {
    __shared__ float wa[8][256], wb[8][256];
    int b = blockIdx.x, c0 = blockIdx.y * 8, t = threadIdx.x;
#pragma unroll
    for (int cc = 0; cc < 8; cc++) {
        wa[cc][t] = w1a[(c0 + cc) * 256 + t];
        wb[cc][t] = w1b[(c0 + cc) * 256 + t];
    }
    __syncthreads();
    const float* xb = x + b * 65536;
    float aA[8], aB[8];
#pragma unroll
    for (int cc = 0; cc < 8; cc++) { aA[cc] = 0.f; aB[cc] = 0.f; }
    const float4* xr = (const float4*)(xb + t * 256);
#pragma unroll 4
    for (int j4 = 0; j4 < 64; j4++) {
        float4 v = xr[j4];
#pragma unroll
        for (int cc = 0; cc < 8; cc++)
            aA[cc] += v.x * wa[cc][j4 * 4] + v.y * wa[cc][j4 * 4 + 1] +
                      v.z * wa[cc][j4 * 4 + 2] + v.w * wa[cc][j4 * 4 + 3];
    }
#pragma unroll 4
    for (int i = 0; i < 256; i++) {
        float xv = xb[i * 256 + t];
#pragma unroll
        for (int cc = 0; cc < 8; cc++) aB[cc] += xv * wb[cc][i];
    }
#pragma unroll
    for (int cc = 0; cc < 8; cc++) {
        g_a1[(b * 128 + c0 + cc) * 256 + t] = aA[cc] + b1a[c0 + cc];
        g_b1[(b * 128 + c0 + cc) * 256 + t] = aB[cc] + b1b[c0 + cc];
    }
}

// ---------------- ks: per-(b,c,mode) bitonic sort + thresholds ----------------
__global__ void __launch_bounds__(256) ks() {
    __shared__ float sv[256];
    __shared__ int si[256];
    int b = blockIdx.x, c = blockIdx.y, t = threadIdx.x;
    int mode = blockIdx.z;
    int base = (b * 128 + c) * 256;
    const float* varr = mode ? g_a1 : g_b1;
    const float* uarr = mode ? g_b1 : g_a1;
    sv[t] = varr[base + t];
    si[t] = t;
    __syncthreads();
    for (int k = 2; k <= 256; k <<= 1) {
        for (int j = k >> 1; j > 0; j >>= 1) {
            int ixj = t ^ j;
            if (ixj > t) {
                bool up = ((t & k) == 0);
                float v0 = sv[t], v1 = sv[ixj];
                if ((v0 > v1) == up) {
                    int i0 = si[t], i1 = si[ixj];
                    sv[t] = v1; sv[ixj] = v0;
                    si[t] = i1; si[ixj] = i0;
                }
            }
            __syncthreads();
        }
    }
    g_svi[mode][base + t] = make_float2(sv[t], __int_as_float(si[t]));
    float u = uarr[base + t];
    float nu = -u;
    int lo = 0, hi = 256;
#pragma unroll
    for (int it = 0; it < 8; it++) {
        int mid = (lo + hi) >> 1;
        if (sv[mid] <= nu) lo = mid + 1; else hi = mid;
    }
    g_uk[mode][base + t] = make_float2(u, __int_as_float(lo));
}

// ---------------- kz: zero the e2n accumulator ----------------
__global__ void kz() { g_np[blockIdx.x * 1024 + threadIdx.x] = 0.f; }

// ---------------- k2s: suffix-sum layer-2; offset folded at scan store; no OS table ----------------
// smem layout reordered so float4-read arrays are 16B-aligned (svis at offset 0).
__global__ void __launch_bounds__(256, 2) k2s(const float* __restrict__ w2a, const float* __restrict__ b2a,
                                              const float* __restrict__ w2b, const float* __restrict__ b2b) {
    extern __shared__ char smem_raw[];
    float2* svis = (float2*)smem_raw;       // [256]  (offset 0 -> float4-aligned rows)
    float2* uks = svis + 256;               // [256]
    float2* segtot = uks + 256;             // [16][16]
    float2* SWp = segtot + 256;             // [257][17] offset-folded suffix pairs (float2 access only)
    float* wtmp = (float*)(SWp + 257 * 17); // [256][17]

    int t = threadIdx.x;
    int p0 = blockIdx.x * 16;
    int bm = blockIdx.y, b = bm >> 1, mode = bm & 1;
    const float* W = mode ? w2b : w2a;
    const float* bias = mode ? b2b : b2a;
    const float2* gsvi = g_svi[mode] + b * 32768;
    const float2* guk = g_uk[mode] + b * 32768;
    float* outp = (mode ? g_b2 : g_a2) + b * 65536;

    int p = t & 15, seg = t >> 4;       // 16 segs x 16 k
    int wlp = t >> 4, wls = t & 15;     // W loader: 16 p rows x 16 k-groups

    if (t < 16) SWp[256 * 17 + t] = make_float2(0.f, 0.f);   // ki=256 -> empty suffix (offset 0)

    float acc[16];
#pragma unroll
    for (int m = 0; m < 16; m++) acc[m] = 0.f;

    const float* wbase = W + (size_t)(p0 + wlp) * 32768;

    for (int c = 0; c < 128; c++) {
        __syncthreads();
        svis[t] = gsvi[c * 256 + t];
        uks[t] = guk[c * 256 + t];
        const float* wrow = wbase + c * 256;
#pragma unroll
        for (int m = 0; m < 4; m++) {
            float4 f = *(const float4*)(wrow + m * 64 + wls * 4);
            int kb = m * 64 + wls * 4;
            wtmp[(kb + 0) * 17 + wlp] = f.x;
            wtmp[(kb + 1) * 17 + wlp] = f.y;
            wtmp[(kb + 2) * 17 + wlp] = f.z;
            wtmp[(kb + 3) * 17 + wlp] = f.w;
        }
        __syncthreads();
        // pass 1: register-resident sv + wv (sv via aligned LDS.128)
        float sv[16], wv[16];
        {
            const float4* svrow = (const float4*)&svis[seg * 16];
#pragma unroll
            for (int j = 0; j < 8; j++) {
                float4 f4 = svrow[j];
                sv[2 * j] = f4.x;
                wv[2 * j] = wtmp[__float_as_int(f4.y) * 17 + p];
                sv[2 * j + 1] = f4.z;
                wv[2 * j + 1] = wtmp[__float_as_int(f4.w) * 17 + p];
            }
        }
        float sumw = 0.f, sumv = 0.f;
#pragma unroll
        for (int e = 15; e >= 0; e--) {
            sumw += wv[e];
            sumv = fmaf(wv[e], sv[e], sumv);
        }
        segtot[seg * 16 + p] = make_float2(sumw, sumv);
        __syncthreads();
        // offset from later segments (ascending), then scan store with offset folded
        float runw = 0.f, runv = 0.f;
        for (int s2 = seg + 1; s2 < 16; s2++) {
            float2 st = segtot[s2 * 16 + p];
            runw += st.x; runv += st.y;
        }
#pragma unroll
        for (int e = 15; e >= 0; e--) {
            runw += wv[e];
            runv = fmaf(wv[e], sv[e], runv);
            SWp[(seg * 16 + e) * 17 + p] = make_float2(runw, runv);
        }
        __syncthreads();
        // main: 2 LDS.64 + 4 FMA per (i,p)
        float2 sw0 = SWp[p];   // k=0 suffix = full total (offset-folded)
#pragma unroll 4
        for (int m = 0; m < 16; m++) {
            float2 ukv = uks[seg * 16 + m];
            int ki = __float_as_int(ukv.y);
            float2 sK = SWp[ki * 17 + p];
            float t1 = fmaf(ukv.x, sK.x, sK.y);
            float t0 = fmaf(ukv.x, sw0.x, sw0.y);
            acc[m] = fmaf(0.33f, t0, fmaf(1.0f - 0.33f, t1, acc[m]));
        }
    }
    float bs = bias[p0 + p];
    float* dst = outp + (size_t)(p0 + p) * 256 + seg * 16;
#pragma unroll
    for (int m = 0; m < 16; m += 4) {
        float4 o = make_float4(acc[m] + bs, acc[m + 1] + bs, acc[m + 2] + bs, acc[m + 3] + bs);
        *(float4*)(dst + m) = o;
    }
}

// ---------------- k3: e2n contraction ----------------
__global__ void __launch_bounds__(256) k3(const float* __restrict__ ew) {
    __shared__ float Bsm[256];
    __shared__ ull Esm[256 * 4];
    int b = blockIdx.x, pc = blockIdx.y, tid = threadIdx.x;
    ull a4[4] = {0ULL, 0ULL, 0ULL, 0ULL};
    for (int p = pc * 4; p < pc * 4 + 4; p++) {
        __syncthreads();
        Bsm[tid] = g_b2[(b * 256 + p) * 256 + tid];
        float e[8];
#pragma unroll
        for (int q = 0; q < 8; q++) e[q] = ew[q * 65536 + p * 256 + tid];
#pragma unroll
        for (int q = 0; q < 4; q++) Esm[tid * 4 + q] = pack2(e[2 * q], e[2 * q + 1]);
        __syncthreads();
        float ai = g_a2[(b * 256 + p) * 256 + tid];
#pragma unroll 4
        for (int j = 0; j < 256; j++) {
            float t = lrelu(ai + Bsm[j]);
            ull ts = pack2(t, t);
            const ull* er = &Esm[j * 4];
            a4[0] = ffma2(er[0], ts, a4[0]);
            a4[1] = ffma2(er[1], ts, a4[1]);
            a4[2] = ffma2(er[2], ts, a4[2]);
            a4[3] = ffma2(er[3], ts, a4[3]);
        }
    }
    float* dst = &g_np[b * 2048 + tid * 8];
#pragma unroll
    for (int q = 0; q < 4; q++) {
        float2 f = unpk(a4[q]);
        atomicAdd(dst + 2 * q, f.x);
        atomicAdd(dst + 2 * q + 1, f.y);
    }
}

// ---------------- k4: GCN / pooling / readout / MLP tail ----------------
__global__ void __launch_bounds__(256) k4(const float* __restrict__ x, const float* __restrict__ e2n_b,
    const float* __restrict__ a11_w, const float* __restrict__ a11_b,
    const float* __restrict__ a12_w, const float* __restrict__ a12_b,
    const float* __restrict__ g1_w,  const float* __restrict__ g1_b,
    const float* __restrict__ a21_w, const float* __restrict__ a21_b,
    const float* __restrict__ a22_w, const float* __restrict__ a22_b,
    const float* __restrict__ d1_w,  const float* __restrict__ d1_b,
    const float* __restrict__ d2_w,  const float* __restrict__ d2_b,
    const float* __restrict__ d3_w,  const float* __restrict__ d3_b,
    float* __restrict__ out) {
    __shared__ uint  m0[256][8];
    __shared__ float nod[256][8];
    __shared__ float dg0[256];
    __shared__ float tp[256];
    __shared__ float sc[256];
    __shared__ float t8[256][8];
    __shared__ int   sel[128];
    __shared__ float hg[128][8];
    __shared__ float on[128][8];
    __shared__ uint  m1[128][4];
    __shared__ float dg1[128];
    __shared__ float z[16];
    __shared__ float z1[128];
    __shared__ float z2[64];

    int b = blockIdx.x, t = threadIdx.x;
    const float* xb = x + b * 65536;
    {
        int w = t >> 5, l = t & 31;
        for (int r = 0; r < 32; r++) {
            int i = w * 32 + r;
            int d = 0;
#pragma unroll
            for (int w8 = 0; w8 < 8; w8++) {
                float xv = xb[i * 256 + w8 * 32 + l];
                uint u = __ballot_sync(0xffffffffu, xv > 0.f);
                if (l == 0) { m0[i][w8] = u; d += __popc(u); }
            }
            if (l == 0) dg0[i] = (float)d;
        }
#pragma unroll
        for (int f = 0; f < 8; f++) nod[t][f] = lrelu(g_np[b * 2048 + t * 8 + f] + e2n_b[f]);
    }
    __syncthreads();
    {
        float s = 0;
#pragma unroll
        for (int f = 0; f < 8; f++) s += nod[t][f] * a11_w[f];
        tp[t] = s / dg0[t];
    }
    __syncthreads();
    {
        float s = 0;
        for (int j = 0; j < 256; j++) if ((m0[t][j >> 5] >> (j & 31)) & 1) s += tp[j];
        sc[t] = lrelu(s + a11_b[0]);
    }
    __syncthreads();
    tp[t] = sc[t] * a12_w[0] / dg0[t];
    __syncthreads();
    {
        float s = 0;
        for (int j = 0; j < 256; j++) if ((m0[t][j >> 5] >> (j & 31)) & 1) s += tp[j];
        sc[t] = 1.f / (1.f + expf(-(s + a12_b[0])));
    }
    __syncthreads();
    {
        float my = sc[t]; int r = 0;
        for (int j = 0; j < 256; j++) {
            float vj = sc[j];
            r += (vj > my) || (vj == my && j < t);
        }
        if (r < 128) sel[r] = t;
    }
    __syncthreads();
    for (int idx = t; idx < 1024; idx += 256) {
        int r = idx >> 3, f = idx & 7; int i = sel[r];
        on[r][f] = nod[i][f] * (1.f + sc[i]);
    }
    if (t < 128) {
        int i = sel[t], d = 0;
#pragma unroll
        for (int w = 0; w < 4; w++) {
            uint u = 0;
            for (int l = 0; l < 32; l++) {
                int j = sel[w * 32 + l];
                u |= ((m0[i][j >> 5] >> (j & 31)) & 1u) << l;
            }
            m1[t][w] = u; d += __popc(u);
        }
        dg1[t] = (float)d;
    }
    __syncthreads();
    if (t < 8) {
        float mx = -1e30f, sm = 0;
        for (int r = 0; r < 128; r++) { float v = on[r][t]; mx = fmaxf(mx, v); sm += v; }
        z[t] = mx; z[8 + t] = sm * (1.f / 128.f);
    }
    __syncthreads();
    for (int idx = t; idx < 1024; idx += 256) {
        int r2 = idx >> 3, fo = idx & 7;
        float s = 0;
#pragma unroll
        for (int f = 0; f < 8; f++) s += on[r2][f] * g1_w[fo * 8 + f];
        t8[r2][fo] = s / dg1[r2];
    }
    __syncthreads();
    for (int idx = t; idx < 1024; idx += 256) {
        int r = idx >> 3, fo = idx & 7;
        float s = 0;
        for (int j = 0; j < 128; j++) if ((m1[r][j >> 5] >> (j & 31)) & 1) s += t8[j][fo];
        hg[r][fo] = s + g1_b[fo];
    }
    __syncthreads();
    if (t < 128) {
        float s = 0;
#pragma unroll
        for (int f = 0; f < 8; f++) s += hg[t][f] * a21_w[f];
        tp[t] = s / dg1[t];
    }
    __syncthreads();
    if (t < 128) {
        float s = 0;
        for (int j = 0; j < 128; j++) if ((m1[t][j >> 5] >> (j & 31)) & 1) s += tp[j];
        sc[t] = lrelu(s + a21_b[0]);
    }
    __syncthreads();
    if (t < 128) tp[t] = sc[t] * a22_w[0] / dg1[t];
    __syncthreads();
    if (t < 128) {
        float s = 0;
        for (int j = 0; j < 128; j++) if ((m1[t][j >> 5] >> (j & 31)) & 1) s += tp[j];
        sc[t] = 1.f / (1.f + expf(-(s + a22_b[0])));
    }
    __syncthreads();
    if (t < 128) {
        float my = sc[t]; int r = 0;
        for (int j = 0; j < 128; j++) {
            float vj = sc[j];
            r += (vj > my) || (vj == my && j < t);
        }
        if (r < 64) sel[r] = t;
    }
    __syncthreads();
    for (int idx = t; idx < 512; idx += 256) {
        int r = idx >> 3, f = idx & 7; int i = sel[r];
        on[r][f] = hg[i][f] * (1.f + sc[i]);
    }
    __syncthreads();
    if (t < 8) {
        float mx = -1e30f, sm = 0;
        for (int r = 0; r < 64; r++) { float v = on[r][t]; mx = fmaxf(mx, v); sm += v; }
        z[t] += mx; z[8 + t] += sm * (1.f / 64.f);
    }
    __syncthreads();
    if (t < 128) {
        float s = d1_b[t];
#pragma unroll
        for (int f = 0; f < 16; f++) s += z[f] * d1_w[t * 16 + f];
        z1[t] = lrelu(s);
    }
    __syncthreads();
    if (t < 64) {
        float s = d2_b[t];
        for (int f = 0; f < 128; f++) s += z1[f] * d2_w[t * 128 + f];
        z2[t] = lrelu(s);
    }
    __syncthreads();
    if (t == 0) {
        float s = d3_b[0];
        for (int f = 0; f < 64; f++) s += z2[f] * d3_w[f];
        out[b] = s;
    }
}

// ---------------- launcher ----------------
extern "C" void kernel_launch(void* const* d_in, const int* in_sizes, int n_in,
                              void* d_out, int out_size) {
    const float* x    = (const float*)d_in[0];
    const float* w1a  = (const float*)d_in[1];
    const float* b1a  = (const float*)d_in[2];
    const float* w1b  = (const float*)d_in[3];
    const float* b1b  = (const float*)d_in[4];
    const float* w2a  = (const float*)d_in[5];
    const float* b2a  = (const float*)d_in[6];
    const float* w2b  = (const float*)d_in[7];
    const float* b2b  = (const float*)d_in[8];
    const float* e2nw = (const float*)d_in[9];
    const float* e2nb = (const float*)d_in[10];
    const float* a11w = (const float*)d_in[11];
    const float* a11b = (const float*)d_in[12];
    const float* a12w = (const float*)d_in[13];
    const float* a12b = (const float*)d_in[14];
    const float* g1w  = (const float*)d_in[15];
    const float* g1b  = (const float*)d_in[16];
    const float* a21w = (const float*)d_in[17];
    const float* a21b = (const float*)d_in[18];
    const float* a22w = (const float*)d_in[19];
    const float* a22b = (const float*)d_in[20];
    const float* d1w  = (const float*)d_in[21];
    const float* d1b  = (const float*)d_in[22];
    const float* d2w  = (const float*)d_in[23];
    const float* d2b  = (const float*)d_in[24];
    const float* d3w  = (const float*)d_in[25];
    const float* d3b  = (const float*)d_in[26];

    // k2s smem: svis 2048 + uks 2048 + segtot 2048 + SWp 257*17*8 + wtmp 256*17*4 = 58,504 B
    const int k2s_smem = 2048 + 2048 + 2048 + 257 * 17 * 8 + 256 * 17 * 4;
    cudaFuncSetAttribute(k2s, cudaFuncAttributeMaxDynamicSharedMemorySize, k2s_smem);

    k1<<<dim3(8, 16), 256>>>(x, w1a, b1a, w1b, b1b);
    ks<<<dim3(8, 128, 2), 256>>>();
    kz<<<16, 1024>>>();
    k2s<<<dim3(16, 16), 256, k2s_smem>>>(w2a, b2a, w2b, b2b);
    k3<<<dim3(8, 64), 256>>>(e2nw);
    k4<<<8, 256>>>(x, e2nb, a11w, a11b, a12w, a12b, g1w, g1b, a21w, a21b,
                   a22w, a22b, d1w, d1b, d2w, d2b, d3w, d3b, (float*)d_out);
}

// round 15
// speedup vs baseline: 1.5749x; 1.2070x over previous
#include <cuda_runtime.h>
#include <math.h>

typedef unsigned long long ull;
typedef unsigned int uint;
#define DV __device__ __forceinline__

// ---------------- scratch (device globals; no allocations) ----------------
__device__ float g_a1[8 * 128 * 256];
__device__ float g_b1[8 * 128 * 256];
__device__ float g_a2[8 * 256 * 256];
__device__ float g_b2[8 * 256 * 256];
__device__ float g_np[8 * 256 * 8];
__device__ float2 g_svi[2][8 * 128 * 256];  // [mode][(b*128+c)*256+k] = {sorted v, idx bits}
__device__ float2 g_uk[2][8 * 128 * 256];   // [mode][(b*128+c)*256+i] = {u, k bits}

DV float lrelu(float x) { return x > 0.f ? x : 0.33f * x; }
DV ull ffma2(ull a, ull b, ull c) {
    ull d; asm("fma.rn.f32x2 %0,%1,%2,%3;" : "=l"(d) : "l"(a), "l"(b), "l"(c)); return d;
}
DV ull pack2(float x, float y) {
    ull d; asm("mov.b64 %0,{%1,%2};" : "=l"(d) : "r"(__float_as_uint(x)), "r"(__float_as_uint(y))); return d;
}
DV float2 unpk(ull v) {
    float2 f; asm("mov.b64 {%0,%1},%2;" : "=f"(f.x), "=f"(f.y) : "l"(v)); return f;
}

// ---------------- k1: layer-1 rank terms (8-c tile) ----------------
__global__ void __launch_bounds__(256) k1(const float* __restrict__ x,
                                          const float* __restrict__ w1a, const float* __restrict__ b1a,
                                          const float* __restrict__ w1b, const float* __restrict__ b1b) {
    __shared__ float wa[8][256], wb[8][256];
    int b = blockIdx.x, c0 = blockIdx.y * 8, t = threadIdx.x;
#pragma unroll
    for (int cc = 0; cc < 8; cc++) {
        wa[cc][t] = w1a[(c0 + cc) * 256 + t];
        wb[cc][t] = w1b[(c0 + cc) * 256 + t];
    }
    __syncthreads();
    const float* xb = x + b * 65536;
    float aA[8], aB[8];
#pragma unroll
    for (int cc = 0; cc < 8; cc++) { aA[cc] = 0.f; aB[cc] = 0.f; }
    const float4* xr = (const float4*)(xb + t * 256);
#pragma unroll 4
    for (int j4 = 0; j4 < 64; j4++) {
        float4 v = xr[j4];
#pragma unroll
        for (int cc = 0; cc < 8; cc++)
            aA[cc] += v.x * wa[cc][j4 * 4] + v.y * wa[cc][j4 * 4 + 1] +
                      v.z * wa[cc][j4 * 4 + 2] + v.w * wa[cc][j4 * 4 + 3];
    }
#pragma unroll 4
    for (int i = 0; i < 256; i++) {
        float xv = xb[i * 256 + t];
#pragma unroll
        for (int cc = 0; cc < 8; cc++) aB[cc] += xv * wb[cc][i];
    }
#pragma unroll
    for (int cc = 0; cc < 8; cc++) {
        g_a1[(b * 128 + c0 + cc) * 256 + t] = aA[cc] + b1a[c0 + cc];
        g_b1[(b * 128 + c0 + cc) * 256 + t] = aB[cc] + b1b[c0 + cc];
    }
}

// ---------------- ks: per-(b,c,mode) bitonic sort + thresholds ----------------
__global__ void __launch_bounds__(256) ks() {
    __shared__ float sv[256];
    __shared__ int si[256];
    int b = blockIdx.x, c = blockIdx.y, t = threadIdx.x;
    int mode = blockIdx.z;
    int base = (b * 128 + c) * 256;
    const float* varr = mode ? g_a1 : g_b1;
    const float* uarr = mode ? g_b1 : g_a1;
    sv[t] = varr[base + t];
    si[t] = t;
    __syncthreads();
    for (int k = 2; k <= 256; k <<= 1) {
        for (int j = k >> 1; j > 0; j >>= 1) {
            int ixj = t ^ j;
            if (ixj > t) {
                bool up = ((t & k) == 0);
                float v0 = sv[t], v1 = sv[ixj];
                if ((v0 > v1) == up) {
                    int i0 = si[t], i1 = si[ixj];
                    sv[t] = v1; sv[ixj] = v0;
                    si[t] = i1; si[ixj] = i0;
                }
            }
            __syncthreads();
        }
    }
    g_svi[mode][base + t] = make_float2(sv[t], __int_as_float(si[t]));
    float u = uarr[base + t];
    float nu = -u;
    int lo = 0, hi = 256;
#pragma unroll
    for (int it = 0; it < 8; it++) {
        int mid = (lo + hi) >> 1;
        if (sv[mid] <= nu) lo = mid + 1; else hi = mid;
    }
    g_uk[mode][base + t] = make_float2(u, __int_as_float(lo));
}

// ---------------- kz: zero the e2n accumulator ----------------
__global__ void kz() { g_np[blockIdx.x * 1024 + threadIdx.x] = 0.f; }

// ---------------- k2s: suffix-sum layer-2; software-pipelined, double-buffered ----------------
// Bit-identical arithmetic to R14; only scheduling/buffering changed.
__global__ void __launch_bounds__(256, 2) k2s(const float* __restrict__ w2a, const float* __restrict__ b2a,
                                              const float* __restrict__ w2b, const float* __restrict__ b2b) {
    extern __shared__ char smem_raw[];
    float2* svis = (float2*)smem_raw;            // [256]      (16B-aligned rows)
    float2* uks = svis + 256;                    // [2][256]   double-buffered
    float2* segtot = uks + 512;                  // [16][16]
    float2* SWp = segtot + 256;                  // [2][257*17] double-buffered suffix pairs
    float* wtmp = (float*)(SWp + 2 * 257 * 17);  // [256][17]

    int t = threadIdx.x;
    int p0 = blockIdx.x * 16;
    int bm = blockIdx.y, b = bm >> 1, mode = bm & 1;
    const float* W = mode ? w2b : w2a;
    const float* bias = mode ? b2b : b2a;
    const float2* gsvi = g_svi[mode] + b * 32768;
    const float2* guk = g_uk[mode] + b * 32768;
    float* outp = (mode ? g_b2 : g_a2) + b * 65536;

    int p = t & 15, seg = t >> 4;       // 16 segs x 16 k
    int wlp = t >> 4, wls = t & 15;     // W loader: 16 p rows x 16 k-groups

    if (t < 16) {                        // ki=256 -> empty suffix, both buffers
        SWp[256 * 17 + t] = make_float2(0.f, 0.f);
        SWp[257 * 17 + 256 * 17 + t] = make_float2(0.f, 0.f);
    }

    float acc[16];
#pragma unroll
    for (int m = 0; m < 16; m++) acc[m] = 0.f;

    const float* wbase = W + (size_t)(p0 + wlp) * 32768;

    // ---- prologue: stage + scan c=0 into buffer 0
    {
        float2 psv = gsvi[t];
        float2 puk = guk[t];
        svis[t] = psv;
        uks[t] = puk;
#pragma unroll
        for (int m = 0; m < 4; m++) {
            float4 f = *(const float4*)(wbase + m * 64 + wls * 4);
            int kb = m * 64 + wls * 4;
            wtmp[(kb + 0) * 17 + wlp] = f.x;
            wtmp[(kb + 1) * 17 + wlp] = f.y;
            wtmp[(kb + 2) * 17 + wlp] = f.z;
            wtmp[(kb + 3) * 17 + wlp] = f.w;
        }
    }
    __syncthreads();
    {
        float sv[16], wv[16];
        const float4* svrow = (const float4*)&svis[seg * 16];
#pragma unroll
        for (int j = 0; j < 8; j++) {
            float4 f4 = svrow[j];
            sv[2 * j] = f4.x;
            wv[2 * j] = wtmp[__float_as_int(f4.y) * 17 + p];
            sv[2 * j + 1] = f4.z;
            wv[2 * j + 1] = wtmp[__float_as_int(f4.w) * 17 + p];
        }
        float sumw = 0.f, sumv = 0.f;
#pragma unroll
        for (int e = 15; e >= 0; e--) {
            sumw += wv[e];
            sumv = fmaf(wv[e], sv[e], sumv);
        }
        segtot[seg * 16 + p] = make_float2(sumw, sumv);
        __syncthreads();
        float runw = 0.f, runv = 0.f;
        for (int s2 = seg + 1; s2 < 16; s2++) {
            float2 st = segtot[s2 * 16 + p];
            runw += st.x; runv += st.y;
        }
#pragma unroll
        for (int e = 15; e >= 0; e--) {
            runw += wv[e];
            runv = fmaf(wv[e], sv[e], runv);
            SWp[(seg * 16 + e) * 17 + p] = make_float2(runw, runv);
        }
    }
    __syncthreads();

    float2 pf_sv, pf_uk;
    float4 pf_w[4];
    for (int c = 0; c < 128; c++) {
        int cur = c & 1, nxt = cur ^ 1;
        // prefetch c+1 (LDG latency hidden under main)
        if (c < 127) {
            const float* wrow = wbase + (c + 1) * 256;
            pf_sv = gsvi[(c + 1) * 256 + t];
            pf_uk = guk[(c + 1) * 256 + t];
#pragma unroll
            for (int m = 0; m < 4; m++)
                pf_w[m] = *(const float4*)(wrow + m * 64 + wls * 4);
        }
        // main(c): reads SWp[cur], uks[cur]; arithmetic identical to R14
        {
            const float2* SW = SWp + cur * (257 * 17);
            float2 sw0 = SW[p];
            const float4* ukrow = (const float4*)&uks[cur * 256 + seg * 16];
#pragma unroll
            for (int mm = 0; mm < 8; mm++) {
                float4 uu = ukrow[mm];
                {
                    int ki = __float_as_int(uu.y);
                    float2 sK = SW[ki * 17 + p];
                    float t1 = fmaf(uu.x, sK.x, sK.y);
                    float t0 = fmaf(uu.x, sw0.x, sw0.y);
                    acc[2 * mm] = fmaf(0.33f, t0, fmaf(1.0f - 0.33f, t1, acc[2 * mm]));
                }
                {
                    int ki = __float_as_int(uu.w);
                    float2 sK = SW[ki * 17 + p];
                    float t1 = fmaf(uu.z, sK.x, sK.y);
                    float t0 = fmaf(uu.z, sw0.x, sw0.y);
                    acc[2 * mm + 1] = fmaf(0.33f, t0, fmaf(1.0f - 0.33f, t1, acc[2 * mm + 1]));
                }
            }
        }
        // stage + scan c+1 into the other buffer
        if (c < 127) {
            svis[t] = pf_sv;
            uks[nxt * 256 + t] = pf_uk;
#pragma unroll
            for (int m = 0; m < 4; m++) {
                int kb = m * 64 + wls * 4;
                wtmp[(kb + 0) * 17 + wlp] = pf_w[m].x;
                wtmp[(kb + 1) * 17 + wlp] = pf_w[m].y;
                wtmp[(kb + 2) * 17 + wlp] = pf_w[m].z;
                wtmp[(kb + 3) * 17 + wlp] = pf_w[m].w;
            }
            __syncthreads();   // A: staging visible
            float2* SWb = SWp + nxt * (257 * 17);
            float sv[16], wv[16];
            const float4* svrow = (const float4*)&svis[seg * 16];
#pragma unroll
            for (int j = 0; j < 8; j++) {
                float4 f4 = svrow[j];
                sv[2 * j] = f4.x;
                wv[2 * j] = wtmp[__float_as_int(f4.y) * 17 + p];
                sv[2 * j + 1] = f4.z;
                wv[2 * j + 1] = wtmp[__float_as_int(f4.w) * 17 + p];
            }
            float sumw = 0.f, sumv = 0.f;
#pragma unroll
            for (int e = 15; e >= 0; e--) {
                sumw += wv[e];
                sumv = fmaf(wv[e], sv[e], sumv);
            }
            segtot[seg * 16 + p] = make_float2(sumw, sumv);
            __syncthreads();   // B
            float runw = 0.f, runv = 0.f;
            for (int s2 = seg + 1; s2 < 16; s2++) {
                float2 st = segtot[s2 * 16 + p];
                runw += st.x; runv += st.y;
            }
#pragma unroll
            for (int e = 15; e >= 0; e--) {
                runw += wv[e];
                runv = fmaf(wv[e], sv[e], runv);
                SWb[(seg * 16 + e) * 17 + p] = make_float2(runw, runv);
            }
            __syncthreads();   // C: SWp[nxt] ready for main(c+1)
        }
    }
    float bs = bias[p0 + p];
    float* dst = outp + (size_t)(p0 + p) * 256 + seg * 16;
#pragma unroll
    for (int m = 0; m < 16; m += 4) {
        float4 o = make_float4(acc[m] + bs, acc[m + 1] + bs, acc[m + 2] + bs, acc[m + 3] + bs);
        *(float4*)(dst + m) = o;
    }
}

// ---------------- k3: e2n contraction ----------------
__global__ void __launch_bounds__(256) k3(const float* __restrict__ ew) {
    __shared__ float Bsm[256];
    __shared__ ull Esm[256 * 4];
    int b = blockIdx.x, pc = blockIdx.y, tid = threadIdx.x;
    ull a4[4] = {0ULL, 0ULL, 0ULL, 0ULL};
    for (int p = pc * 4; p < pc * 4 + 4; p++) {
        __syncthreads();
        Bsm[tid] = g_b2[(b * 256 + p) * 256 + tid];
        float e[8];
#pragma unroll
        for (int q = 0; q < 8; q++) e[q] = ew[q * 65536 + p * 256 + tid];
#pragma unroll
        for (int q = 0; q < 4; q++) Esm[tid * 4 + q] = pack2(e[2 * q], e[2 * q + 1]);
        __syncthreads();
        float ai = g_a2[(b * 256 + p) * 256 + tid];
#pragma unroll 4
        for (int j = 0; j < 256; j++) {
            float t = lrelu(ai + Bsm[j]);
            ull ts = pack2(t, t);
            const ull* er = &Esm[j * 4];
            a4[0] = ffma2(er[0], ts, a4[0]);
            a4[1] = ffma2(er[1], ts, a4[1]);
            a4[2] = ffma2(er[2], ts, a4[2]);
            a4[3] = ffma2(er[3], ts, a4[3]);
        }
    }
    float* dst = &g_np[b * 2048 + tid * 8];
#pragma unroll
    for (int q = 0; q < 4; q++) {
        float2 f = unpk(a4[q]);
        atomicAdd(dst + 2 * q, f.x);
        atomicAdd(dst + 2 * q + 1, f.y);
    }
}

// ---------------- k4: GCN / pooling / readout / MLP tail ----------------
__global__ void __launch_bounds__(256) k4(const float* __restrict__ x, const float* __restrict__ e2n_b,
    const float* __restrict__ a11_w, const float* __restrict__ a11_b,
    const float* __restrict__ a12_w, const float* __restrict__ a12_b,
    const float* __restrict__ g1_w,  const float* __restrict__ g1_b,
    const float* __restrict__ a21_w, const float* __restrict__ a21_b,
    const float* __restrict__ a22_w, const float* __restrict__ a22_b,
    const float* __restrict__ d1_w,  const float* __restrict__ d1_b,
    const float* __restrict__ d2_w,  const float* __restrict__ d2_b,
    const float* __restrict__ d3_w,  const float* __restrict__ d3_b,
    float* __restrict__ out) {
    __shared__ uint  m0[256][8];
    __shared__ float nod[256][8];
    __shared__ float dg0[256];
    __shared__ float tp[256];
    __shared__ float sc[256];
    __shared__ float t8[256][8];
    __shared__ int   sel[128];
    __shared__ float hg[128][8];
    __shared__ float on[128][8];
    __shared__ uint  m1[128][4];
    __shared__ float dg1[128];
    __shared__ float z[16];
    __shared__ float z1[128];
    __shared__ float z2[64];

    int b = blockIdx.x, t = threadIdx.x;
    const float* xb = x + b * 65536;
    {
        int w = t >> 5, l = t & 31;
        for (int r = 0; r < 32; r++) {
            int i = w * 32 + r;
            int d = 0;
#pragma unroll
            for (int w8 = 0; w8 < 8; w8++) {
                float xv = xb[i * 256 + w8 * 32 + l];
                uint u = __ballot_sync(0xffffffffu, xv > 0.f);
                if (l == 0) { m0[i][w8] = u; d += __popc(u); }
            }
            if (l == 0) dg0[i] = (float)d;
        }
#pragma unroll
        for (int f = 0; f < 8; f++) nod[t][f] = lrelu(g_np[b * 2048 + t * 8 + f] + e2n_b[f]);
    }
    __syncthreads();
    {
        float s = 0;
#pragma unroll
        for (int f = 0; f < 8; f++) s += nod[t][f] * a11_w[f];
        tp[t] = s / dg0[t];
    }
    __syncthreads();
    {
        float s = 0;
        for (int j = 0; j < 256; j++) if ((m0[t][j >> 5] >> (j & 31)) & 1) s += tp[j];
        sc[t] = lrelu(s + a11_b[0]);
    }
    __syncthreads();
    tp[t] = sc[t] * a12_w[0] / dg0[t];
    __syncthreads();
    {
        float s = 0;
        for (int j = 0; j < 256; j++) if ((m0[t][j >> 5] >> (j & 31)) & 1) s += tp[j];
        sc[t] = 1.f / (1.f + expf(-(s + a12_b[0])));
    }
    __syncthreads();
    {
        float my = sc[t]; int r = 0;
        for (int j = 0; j < 256; j++) {
            float vj = sc[j];
            r += (vj > my) || (vj == my && j < t);
        }
        if (r < 128) sel[r] = t;
    }
    __syncthreads();
    for (int idx = t; idx < 1024; idx += 256) {
        int r = idx >> 3, f = idx & 7; int i = sel[r];
        on[r][f] = nod[i][f] * (1.f + sc[i]);
    }
    if (t < 128) {
        int i = sel[t], d = 0;
#pragma unroll
        for (int w = 0; w < 4; w++) {
            uint u = 0;
            for (int l = 0; l < 32; l++) {
                int j = sel[w * 32 + l];
                u |= ((m0[i][j >> 5] >> (j & 31)) & 1u) << l;
            }
            m1[t][w] = u; d += __popc(u);
        }
        dg1[t] = (float)d;
    }
    __syncthreads();
    if (t < 8) {
        float mx = -1e30f, sm = 0;
        for (int r = 0; r < 128; r++) { float v = on[r][t]; mx = fmaxf(mx, v); sm += v; }
        z[t] = mx; z[8 + t] = sm * (1.f / 128.f);
    }
    __syncthreads();
    for (int idx = t; idx < 1024; idx += 256) {
        int r2 = idx >> 3, fo = idx & 7;
        float s = 0;
#pragma unroll
        for (int f = 0; f < 8; f++) s += on[r2][f] * g1_w[fo * 8 + f];
        t8[r2][fo] = s / dg1[r2];
    }
    __syncthreads();
    for (int idx = t; idx < 1024; idx += 256) {
        int r = idx >> 3, fo = idx & 7;
        float s = 0;
        for (int j = 0; j < 128; j++) if ((m1[r][j >> 5] >> (j & 31)) & 1) s += t8[j][fo];
        hg[r][fo] = s + g1_b[fo];
    }
    __syncthreads();
    if (t < 128) {
        float s = 0;
#pragma unroll
        for (int f = 0; f < 8; f++) s += hg[t][f] * a21_w[f];
        tp[t] = s / dg1[t];
    }
    __syncthreads();
    if (t < 128) {
        float s = 0;
        for (int j = 0; j < 128; j++) if ((m1[t][j >> 5] >> (j & 31)) & 1) s += tp[j];
        sc[t] = lrelu(s + a21_b[0]);
    }
    __syncthreads();
    if (t < 128) tp[t] = sc[t] * a22_w[0] / dg1[t];
    __syncthreads();
    if (t < 128) {
        float s = 0;
        for (int j = 0; j < 128; j++) if ((m1[t][j >> 5] >> (j & 31)) & 1) s += tp[j];
        sc[t] = 1.f / (1.f + expf(-(s + a22_b[0])));
    }
    __syncthreads();
    if (t < 128) {
        float my = sc[t]; int r = 0;
        for (int j = 0; j < 128; j++) {
            float vj = sc[j];
            r += (vj > my) || (vj == my && j < t);
        }
        if (r < 64) sel[r] = t;
    }
    __syncthreads();
    for (int idx = t; idx < 512; idx += 256) {
        int r = idx >> 3, f = idx & 7; int i = sel[r];
        on[r][f] = hg[i][f] * (1.f + sc[i]);
    }
    __syncthreads();
    if (t < 8) {
        float mx = -1e30f, sm = 0;
        for (int r = 0; r < 64; r++) { float v = on[r][t]; mx = fmaxf(mx, v); sm += v; }
        z[t] += mx; z[8 + t] += sm * (1.f / 64.f);
    }
    __syncthreads();
    if (t < 128) {
        float s = d1_b[t];
#pragma unroll
        for (int f = 0; f < 16; f++) s += z[f] * d1_w[t * 16 + f];
        z1[t] = lrelu(s);
    }
    __syncthreads();
    if (t < 64) {
        float s = d2_b[t];
        for (int f = 0; f < 128; f++) s += z1[f] * d2_w[t * 128 + f];
        z2[t] = lrelu(s);
    }
    __syncthreads();
    if (t == 0) {
        float s = d3_b[0];
        for (int f = 0; f < 64; f++) s += z2[f] * d3_w[f];
        out[b] = s;
    }
}

// ---------------- launcher ----------------
extern "C" void kernel_launch(void* const* d_in, const int* in_sizes, int n_in,
                              void* d_out, int out_size) {
    const float* x    = (const float*)d_in[0];
    const float* w1a  = (const float*)d_in[1];
    const float* b1a  = (const float*)d_in[2];
    const float* w1b  = (const float*)d_in[3];
    const float* b1b  = (const float*)d_in[4];
    const float* w2a  = (const float*)d_in[5];
    const float* b2a  = (const float*)d_in[6];
    const float* w2b  = (const float*)d_in[7];
    const float* b2b  = (const float*)d_in[8];
    const float* e2nw = (const float*)d_in[9];
    const float* e2nb = (const float*)d_in[10];
    const float* a11w = (const float*)d_in[11];
    const float* a11b = (const float*)d_in[12];
    const float* a12w = (const float*)d_in[13];
    const float* a12b = (const float*)d_in[14];
    const float* g1w  = (const float*)d_in[15];
    const float* g1b  = (const float*)d_in[16];
    const float* a21w = (const float*)d_in[17];
    const float* a21b = (const float*)d_in[18];
    const float* a22w = (const float*)d_in[19];
    const float* a22b = (const float*)d_in[20];
    const float* d1w  = (const float*)d_in[21];
    const float* d1b  = (const float*)d_in[22];
    const float* d2w  = (const float*)d_in[23];
    const float* d2b  = (const float*)d_in[24];
    const float* d3w  = (const float*)d_in[25];
    const float* d3b  = (const float*)d_in[26];

    // k2s smem: svis 2048 + uks 4096 + segtot 2048 + SWp 2*257*17*8 + wtmp 256*17*4 = 95,504 B
    const int k2s_smem = 2048 + 4096 + 2048 + 2 * 257 * 17 * 8 + 256 * 17 * 4;
    cudaFuncSetAttribute(k2s, cudaFuncAttributeMaxDynamicSharedMemorySize, k2s_smem);

    k1<<<dim3(8, 16), 256>>>(x, w1a, b1a, w1b, b1b);
    ks<<<dim3(8, 128, 2), 256>>>();
    kz<<<16, 1024>>>();
    k2s<<<dim3(16, 16), 256, k2s_smem>>>(w2a, b2a, w2b, b2b);
    k3<<<dim3(8, 64), 256>>>(e2nw);
    k4<<<8, 256>>>(x, e2nb, a11w, a11b, a12w, a12b, g1w, g1b, a21w, a21b,
                   a22w, a22b, d1w, d1b, d2w, d2b, d3w, d3b, (float*)d_out);
}

// round 16
// speedup vs baseline: 1.6483x; 1.0466x over previous
#include <cuda_runtime.h>
#include <math.h>

typedef unsigned long long ull;
typedef unsigned int uint;
#define DV __device__ __forceinline__

// ---------------- scratch (device globals; no allocations) ----------------
__device__ float g_a1[8 * 128 * 256];
__device__ float g_b1[8 * 128 * 256];
__device__ float g_a2[8 * 256 * 256];
__device__ float g_b2[8 * 256 * 256];
__device__ float g_np[8 * 256 * 8];
__device__ float2 g_svi[2][8 * 128 * 256];  // [mode][(b*128+c)*256+k] = {sorted v, idx bits}
__device__ float2 g_uk[2][8 * 128 * 256];   // [mode][(b*128+c)*256+i] = {u, k bits}
__device__ float g_part[4][16][65536];      // c-split partials

DV float lrelu(float x) { return x > 0.f ? x : 0.33f * x; }
DV ull ffma2(ull a, ull b, ull c) {
    ull d; asm("fma.rn.f32x2 %0,%1,%2,%3;" : "=l"(d) : "l"(a), "l"(b), "l"(c)); return d;
}
DV ull pack2(float x, float y) {
    ull d; asm("mov.b64 %0,{%1,%2};" : "=l"(d) : "r"(__float_as_uint(x)), "r"(__float_as_uint(y))); return d;
}
DV float2 unpk(ull v) {
    float2 f; asm("mov.b64 {%0,%1},%2;" : "=f"(f.x), "=f"(f.y) : "l"(v)); return f;
}

// ---------------- k1: layer-1 rank terms (8-c tile) ----------------
__global__ void __launch_bounds__(256) k1(const float* __restrict__ x,
                                          const float* __restrict__ w1a, const float* __restrict__ b1a,
                                          const float* __restrict__ w1b, const float* __restrict__ b1b) {
    __shared__ float wa[8][256], wb[8][256];
    int b = blockIdx.x, c0 = blockIdx.y * 8, t = threadIdx.x;
#pragma unroll
    for (int cc = 0; cc < 8; cc++) {
        wa[cc][t] = w1a[(c0 + cc) * 256 + t];
        wb[cc][t] = w1b[(c0 + cc) * 256 + t];
    }
    __syncthreads();
    const float* xb = x + b * 65536;
    float aA[8], aB[8];
#pragma unroll
    for (int cc = 0; cc < 8; cc++) { aA[cc] = 0.f; aB[cc] = 0.f; }
    const float4* xr = (const float4*)(xb + t * 256);
#pragma unroll 4
    for (int j4 = 0; j4 < 64; j4++) {
        float4 v = xr[j4];
#pragma unroll
        for (int cc = 0; cc < 8; cc++)
            aA[cc] += v.x * wa[cc][j4 * 4] + v.y * wa[cc][j4 * 4 + 1] +
                      v.z * wa[cc][j4 * 4 + 2] + v.w * wa[cc][j4 * 4 + 3];
    }
#pragma unroll 4
    for (int i = 0; i < 256; i++) {
        float xv = xb[i * 256 + t];
#pragma unroll
        for (int cc = 0; cc < 8; cc++) aB[cc] += xv * wb[cc][i];
    }
#pragma unroll
    for (int cc = 0; cc < 8; cc++) {
        g_a1[(b * 128 + c0 + cc) * 256 + t] = aA[cc] + b1a[c0 + cc];
        g_b1[(b * 128 + c0 + cc) * 256 + t] = aB[cc] + b1b[c0 + cc];
    }
}

// ---------------- ks: per-(b,c,mode) bitonic sort + thresholds ----------------
__global__ void __launch_bounds__(256) ks() {
    __shared__ float sv[256];
    __shared__ int si[256];
    int b = blockIdx.x, c = blockIdx.y, t = threadIdx.x;
    int mode = blockIdx.z;
    int base = (b * 128 + c) * 256;
    const float* varr = mode ? g_a1 : g_b1;
    const float* uarr = mode ? g_b1 : g_a1;
    sv[t] = varr[base + t];
    si[t] = t;
    __syncthreads();
    for (int k = 2; k <= 256; k <<= 1) {
        for (int j = k >> 1; j > 0; j >>= 1) {
            int ixj = t ^ j;
            if (ixj > t) {
                bool up = ((t & k) == 0);
                float v0 = sv[t], v1 = sv[ixj];
                if ((v0 > v1) == up) {
                    int i0 = si[t], i1 = si[ixj];
                    sv[t] = v1; sv[ixj] = v0;
                    si[t] = i1; si[ixj] = i0;
                }
            }
            __syncthreads();
        }
    }
    g_svi[mode][base + t] = make_float2(sv[t], __int_as_float(si[t]));
    float u = uarr[base + t];
    float nu = -u;
    int lo = 0, hi = 256;
#pragma unroll
    for (int it = 0; it < 8; it++) {
        int mid = (lo + hi) >> 1;
        if (sv[mid] <= nu) lo = mid + 1; else hi = mid;
    }
    g_uk[mode][base + t] = make_float2(u, __int_as_float(lo));
}

// ---------------- kz: zero the e2n accumulator ----------------
__global__ void kz() { g_np[blockIdx.x * 1024 + threadIdx.x] = 0.f; }

// ---------------- k2s: suffix-sum layer-2; pipelined, double-buffered, c-split x4 ----------------
__global__ void __launch_bounds__(256, 2) k2s(const float* __restrict__ w2a,
                                              const float* __restrict__ w2b) {
    extern __shared__ char smem_raw[];
    float2* svis = (float2*)smem_raw;            // [256]      (16B-aligned rows)
    float2* uks = svis + 256;                    // [2][256]   double-buffered
    float2* segtot = uks + 512;                  // [16][16]
    float2* SWp = segtot + 256;                  // [2][257*17] double-buffered suffix pairs
    float* wtmp = (float*)(SWp + 2 * 257 * 17);  // [256][17]

    int t = threadIdx.x;
    int p0 = blockIdx.x * 16;
    int bm = blockIdx.y, b = bm >> 1, mode = bm & 1;
    int slice = blockIdx.z;
    int c0 = slice * 32;
    const float* W = mode ? w2b : w2a;
    const float2* gsvi = g_svi[mode] + b * 32768;
    const float2* guk = g_uk[mode] + b * 32768;

    int p = t & 15, seg = t >> 4;       // 16 segs x 16 k
    int wlp = t >> 4, wls = t & 15;     // W loader: 16 p rows x 16 k-groups

    if (t < 16) {                        // ki=256 -> empty suffix, both buffers
        SWp[256 * 17 + t] = make_float2(0.f, 0.f);
        SWp[257 * 17 + 256 * 17 + t] = make_float2(0.f, 0.f);
    }

    float acc[16];
#pragma unroll
    for (int m = 0; m < 16; m++) acc[m] = 0.f;

    const float* wbase = W + (size_t)(p0 + wlp) * 32768;

    // ---- prologue: stage + scan c=c0 into buffer 0
    {
        float2 psv = gsvi[c0 * 256 + t];
        float2 puk = guk[c0 * 256 + t];
        svis[t] = psv;
        uks[t] = puk;
        const float* wrow = wbase + c0 * 256;
#pragma unroll
        for (int m = 0; m < 4; m++) {
            float4 f = *(const float4*)(wrow + m * 64 + wls * 4);
            int kb = m * 64 + wls * 4;
            wtmp[(kb + 0) * 17 + wlp] = f.x;
            wtmp[(kb + 1) * 17 + wlp] = f.y;
            wtmp[(kb + 2) * 17 + wlp] = f.z;
            wtmp[(kb + 3) * 17 + wlp] = f.w;
        }
    }
    __syncthreads();
    {
        float sv[16], wv[16];
        const float4* svrow = (const float4*)&svis[seg * 16];
#pragma unroll
        for (int j = 0; j < 8; j++) {
            float4 f4 = svrow[j];
            sv[2 * j] = f4.x;
            wv[2 * j] = wtmp[__float_as_int(f4.y) * 17 + p];
            sv[2 * j + 1] = f4.z;
            wv[2 * j + 1] = wtmp[__float_as_int(f4.w) * 17 + p];
        }
        float sumw = 0.f, sumv = 0.f;
#pragma unroll
        for (int e = 15; e >= 0; e--) {
            sumw += wv[e];
            sumv = fmaf(wv[e], sv[e], sumv);
        }
        segtot[seg * 16 + p] = make_float2(sumw, sumv);
        __syncthreads();
        float runw = 0.f, runv = 0.f;
        for (int s2 = seg + 1; s2 < 16; s2++) {
            float2 st = segtot[s2 * 16 + p];
            runw += st.x; runv += st.y;
        }
#pragma unroll
        for (int e = 15; e >= 0; e--) {
            runw += wv[e];
            runv = fmaf(wv[e], sv[e], runv);
            SWp[(seg * 16 + e) * 17 + p] = make_float2(runw, runv);
        }
    }
    __syncthreads();

    float2 pf_sv, pf_uk;
    float4 pf_w[4];
    for (int cc = 0; cc < 32; cc++) {
        int c = c0 + cc;
        int cur = cc & 1, nxt = cur ^ 1;
        // prefetch c+1 (LDG latency hidden under main)
        if (cc < 31) {
            const float* wrow = wbase + (c + 1) * 256;
            pf_sv = gsvi[(c + 1) * 256 + t];
            pf_uk = guk[(c + 1) * 256 + t];
#pragma unroll
            for (int m = 0; m < 4; m++)
                pf_w[m] = *(const float4*)(wrow + m * 64 + wls * 4);
        }
        // main(c): reads SWp[cur], uks[cur]
        {
            const float2* SW = SWp + cur * (257 * 17);
            float2 sw0 = SW[p];
            const float4* ukrow = (const float4*)&uks[cur * 256 + seg * 16];
#pragma unroll
            for (int mm = 0; mm < 8; mm++) {
                float4 uu = ukrow[mm];
                {
                    int ki = __float_as_int(uu.y);
                    float2 sK = SW[ki * 17 + p];
                    float t1 = fmaf(uu.x, sK.x, sK.y);
                    float t0 = fmaf(uu.x, sw0.x, sw0.y);
                    acc[2 * mm] = fmaf(0.33f, t0, fmaf(1.0f - 0.33f, t1, acc[2 * mm]));
                }
                {
                    int ki = __float_as_int(uu.w);
                    float2 sK = SW[ki * 17 + p];
                    float t1 = fmaf(uu.z, sK.x, sK.y);
                    float t0 = fmaf(uu.z, sw0.x, sw0.y);
                    acc[2 * mm + 1] = fmaf(0.33f, t0, fmaf(1.0f - 0.33f, t1, acc[2 * mm + 1]));
                }
            }
        }
        // stage + scan c+1 into the other buffer
        if (cc < 31) {
            svis[t] = pf_sv;
            uks[nxt * 256 + t] = pf_uk;
#pragma unroll
            for (int m = 0; m < 4; m++) {
                int kb = m * 64 + wls * 4;
                wtmp[(kb + 0) * 17 + wlp] = pf_w[m].x;
                wtmp[(kb + 1) * 17 + wlp] = pf_w[m].y;
                wtmp[(kb + 2) * 17 + wlp] = pf_w[m].z;
                wtmp[(kb + 3) * 17 + wlp] = pf_w[m].w;
            }
            __syncthreads();   // A: staging visible
            float2* SWb = SWp + nxt * (257 * 17);
            float sv[16], wv[16];
            const float4* svrow = (const float4*)&svis[seg * 16];
#pragma unroll
            for (int j = 0; j < 8; j++) {
                float4 f4 = svrow[j];
                sv[2 * j] = f4.x;
                wv[2 * j] = wtmp[__float_as_int(f4.y) * 17 + p];
                sv[2 * j + 1] = f4.z;
                wv[2 * j + 1] = wtmp[__float_as_int(f4.w) * 17 + p];
            }
            float sumw = 0.f, sumv = 0.f;
#pragma unroll
            for (int e = 15; e >= 0; e--) {
                sumw += wv[e];
                sumv = fmaf(wv[e], sv[e], sumv);
            }
            segtot[seg * 16 + p] = make_float2(sumw, sumv);
            __syncthreads();   // B
            float runw = 0.f, runv = 0.f;
            for (int s2 = seg + 1; s2 < 16; s2++) {
                float2 st = segtot[s2 * 16 + p];
                runw += st.x; runv += st.y;
            }
#pragma unroll
            for (int e = 15; e >= 0; e--) {
                runw += wv[e];
                runv = fmaf(wv[e], sv[e], runv);
                SWb[(seg * 16 + e) * 17 + p] = make_float2(runw, runv);
            }
            __syncthreads();   // C: SWp[nxt] ready for main(c+1)
        }
    }
    // epilogue: partial write (no bias; reduced in kr4)
    float* dst = &g_part[slice][bm][0] + (size_t)(p0 + p) * 256 + seg * 16;
#pragma unroll
    for (int m = 0; m < 16; m += 4) {
        float4 o = make_float4(acc[m], acc[m + 1], acc[m + 2], acc[m + 3]);
        *(float4*)(dst + m) = o;
    }
}

// ---------------- kr4: deterministic 4-slice reduction + bias ----------------
__global__ void __launch_bounds__(256) kr4(const float* __restrict__ b2a,
                                           const float* __restrict__ b2b) {
    int idx = (blockIdx.x * 256 + threadIdx.x) * 4;
    int bm = idx >> 16, rem = idx & 65535;
    int p = rem >> 8;
    float4 s = *(const float4*)&g_part[0][bm][rem];
#pragma unroll
    for (int sl = 1; sl < 4; sl++) {
        float4 u = *(const float4*)&g_part[sl][bm][rem];
        s.x += u.x; s.y += u.y; s.z += u.z; s.w += u.w;
    }
    float bias = (bm & 1) ? b2b[p] : b2a[p];
    s.x += bias; s.y += bias; s.z += bias; s.w += bias;
    float* out = ((bm & 1) ? g_b2 : g_a2) + (bm >> 1) * 65536 + rem;
    *(float4*)out = s;
}

// ---------------- k3: e2n contraction ----------------
__global__ void __launch_bounds__(256) k3(const float* __restrict__ ew) {
    __shared__ float Bsm[256];
    __shared__ ull Esm[256 * 4];
    int b = blockIdx.x, pc = blockIdx.y, tid = threadIdx.x;
    ull a4[4] = {0ULL, 0ULL, 0ULL, 0ULL};
    for (int p = pc * 4; p < pc * 4 + 4; p++) {
        __syncthreads();
        Bsm[tid] = g_b2[(b * 256 + p) * 256 + tid];
        float e[8];
#pragma unroll
        for (int q = 0; q < 8; q++) e[q] = ew[q * 65536 + p * 256 + tid];
#pragma unroll
        for (int q = 0; q < 4; q++) Esm[tid * 4 + q] = pack2(e[2 * q], e[2 * q + 1]);
        __syncthreads();
        float ai = g_a2[(b * 256 + p) * 256 + tid];
#pragma unroll 4
        for (int j = 0; j < 256; j++) {
            float t = lrelu(ai + Bsm[j]);
            ull ts = pack2(t, t);
            const ull* er = &Esm[j * 4];
            a4[0] = ffma2(er[0], ts, a4[0]);
            a4[1] = ffma2(er[1], ts, a4[1]);
            a4[2] = ffma2(er[2], ts, a4[2]);
            a4[3] = ffma2(er[3], ts, a4[3]);
        }
    }
    float* dst = &g_np[b * 2048 + tid * 8];
#pragma unroll
    for (int q = 0; q < 4; q++) {
        float2 f = unpk(a4[q]);
        atomicAdd(dst + 2 * q, f.x);
        atomicAdd(dst + 2 * q + 1, f.y);
    }
}

// ---------------- k4: GCN / pooling / readout / MLP tail ----------------
__global__ void __launch_bounds__(256) k4(const float* __restrict__ x, const float* __restrict__ e2n_b,
    const float* __restrict__ a11_w, const float* __restrict__ a11_b,
    const float* __restrict__ a12_w, const float* __restrict__ a12_b,
    const float* __restrict__ g1_w,  const float* __restrict__ g1_b,
    const float* __restrict__ a21_w, const float* __restrict__ a21_b,
    const float* __restrict__ a22_w, const float* __restrict__ a22_b,
    const float* __restrict__ d1_w,  const float* __restrict__ d1_b,
    const float* __restrict__ d2_w,  const float* __restrict__ d2_b,
    const float* __restrict__ d3_w,  const float* __restrict__ d3_b,
    float* __restrict__ out) {
    __shared__ uint  m0[256][8];
    __shared__ float nod[256][8];
    __shared__ float dg0[256];
    __shared__ float tp[256];
    __shared__ float sc[256];
    __shared__ float t8[256][8];
    __shared__ int   sel[128];
    __shared__ float hg[128][8];
    __shared__ float on[128][8];
    __shared__ uint  m1[128][4];
    __shared__ float dg1[128];
    __shared__ float z[16];
    __shared__ float z1[128];
    __shared__ float z2[64];

    int b = blockIdx.x, t = threadIdx.x;
    const float* xb = x + b * 65536;
    {
        int w = t >> 5, l = t & 31;
        for (int r = 0; r < 32; r++) {
            int i = w * 32 + r;
            int d = 0;
#pragma unroll
            for (int w8 = 0; w8 < 8; w8++) {
                float xv = xb[i * 256 + w8 * 32 + l];
                uint u = __ballot_sync(0xffffffffu, xv > 0.f);
                if (l == 0) { m0[i][w8] = u; d += __popc(u); }
            }
            if (l == 0) dg0[i] = (float)d;
        }
#pragma unroll
        for (int f = 0; f < 8; f++) nod[t][f] = lrelu(g_np[b * 2048 + t * 8 + f] + e2n_b[f]);
    }
    __syncthreads();
    {
        float s = 0;
#pragma unroll
        for (int f = 0; f < 8; f++) s += nod[t][f] * a11_w[f];
        tp[t] = s / dg0[t];
    }
    __syncthreads();
    {
        float s = 0;
        for (int j = 0; j < 256; j++) if ((m0[t][j >> 5] >> (j & 31)) & 1) s += tp[j];
        sc[t] = lrelu(s + a11_b[0]);
    }
    __syncthreads();
    tp[t] = sc[t] * a12_w[0] / dg0[t];
    __syncthreads();
    {
        float s = 0;
        for (int j = 0; j < 256; j++) if ((m0[t][j >> 5] >> (j & 31)) & 1) s += tp[j];
        sc[t] = 1.f / (1.f + expf(-(s + a12_b[0])));
    }
    __syncthreads();
    {
        float my = sc[t]; int r = 0;
        for (int j = 0; j < 256; j++) {
            float vj = sc[j];
            r += (vj > my) || (vj == my && j < t);
        }
        if (r < 128) sel[r] = t;
    }
    __syncthreads();
    for (int idx = t; idx < 1024; idx += 256) {
        int r = idx >> 3, f = idx & 7; int i = sel[r];
        on[r][f] = nod[i][f] * (1.f + sc[i]);
    }
    if (t < 128) {
        int i = sel[t], d = 0;
#pragma unroll
        for (int w = 0; w < 4; w++) {
            uint u = 0;
            for (int l = 0; l < 32; l++) {
                int j = sel[w * 32 + l];
                u |= ((m0[i][j >> 5] >> (j & 31)) & 1u) << l;
            }
            m1[t][w] = u; d += __popc(u);
        }
        dg1[t] = (float)d;
    }
    __syncthreads();
    if (t < 8) {
        float mx = -1e30f, sm = 0;
        for (int r = 0; r < 128; r++) { float v = on[r][t]; mx = fmaxf(mx, v); sm += v; }
        z[t] = mx; z[8 + t] = sm * (1.f / 128.f);
    }
    __syncthreads();
    for (int idx = t; idx < 1024; idx += 256) {
        int r2 = idx >> 3, fo = idx & 7;
        float s = 0;
#pragma unroll
        for (int f = 0; f < 8; f++) s += on[r2][f] * g1_w[fo * 8 + f];
        t8[r2][fo] = s / dg1[r2];
    }
    __syncthreads();
    for (int idx = t; idx < 1024; idx += 256) {
        int r = idx >> 3, fo = idx & 7;
        float s = 0;
        for (int j = 0; j < 128; j++) if ((m1[r][j >> 5] >> (j & 31)) & 1) s += t8[j][fo];
        hg[r][fo] = s + g1_b[fo];
    }
    __syncthreads();
    if (t < 128) {
        float s = 0;
#pragma unroll
        for (int f = 0; f < 8; f++) s += hg[t][f] * a21_w[f];
        tp[t] = s / dg1[t];
    }
    __syncthreads();
    if (t < 128) {
        float s = 0;
        for (int j = 0; j < 128; j++) if ((m1[t][j >> 5] >> (j & 31)) & 1) s += tp[j];
        sc[t] = lrelu(s + a21_b[0]);
    }
    __syncthreads();
    if (t < 128) tp[t] = sc[t] * a22_w[0] / dg1[t];
    __syncthreads();
    if (t < 128) {
        float s = 0;
        for (int j = 0; j < 128; j++) if ((m1[t][j >> 5] >> (j & 31)) & 1) s += tp[j];
        sc[t] = 1.f / (1.f + expf(-(s + a22_b[0])));
    }
    __syncthreads();
    if (t < 128) {
        float my = sc[t]; int r = 0;
        for (int j = 0; j < 128; j++) {
            float vj = sc[j];
            r += (vj > my) || (vj == my && j < t);
        }
        if (r < 64) sel[r] = t;
    }
    __syncthreads();
    for (int idx = t; idx < 512; idx += 256) {
        int r = idx >> 3, f = idx & 7; int i = sel[r];
        on[r][f] = hg[i][f] * (1.f + sc[i]);
    }
    __syncthreads();
    if (t < 8) {
        float mx = -1e30f, sm = 0;
        for (int r = 0; r < 64; r++) { float v = on[r][t]; mx = fmaxf(mx, v); sm += v; }
        z[t] += mx; z[8 + t] += sm * (1.f / 64.f);
    }
    __syncthreads();
    if (t < 128) {
        float s = d1_b[t];
#pragma unroll
        for (int f = 0; f < 16; f++) s += z[f] * d1_w[t * 16 + f];
        z1[t] = lrelu(s);
    }
    __syncthreads();
    if (t < 64) {
        float s = d2_b[t];
        for (int f = 0; f < 128; f++) s += z1[f] * d2_w[t * 128 + f];
        z2[t] = lrelu(s);
    }
    __syncthreads();
    if (t == 0) {
        float s = d3_b[0];
        for (int f = 0; f < 64; f++) s += z2[f] * d3_w[f];
        out[b] = s;
    }
}

// ---------------- launcher ----------------
extern "C" void kernel_launch(void* const* d_in, const int* in_sizes, int n_in,
                              void* d_out, int out_size) {
    const float* x    = (const float*)d_in[0];
    const float* w1a  = (const float*)d_in[1];
    const float* b1a  = (const float*)d_in[2];
    const float* w1b  = (const float*)d_in[3];
    const float* b1b  = (const float*)d_in[4];
    const float* w2a  = (const float*)d_in[5];
    const float* b2a  = (const float*)d_in[6];
    const float* w2b  = (const float*)d_in[7];
    const float* b2b  = (const float*)d_in[8];
    const float* e2nw = (const float*)d_in[9];
    const float* e2nb = (const float*)d_in[10];
    const float* a11w = (const float*)d_in[11];
    const float* a11b = (const float*)d_in[12];
    const float* a12w = (const float*)d_in[13];
    const float* a12b = (const float*)d_in[14];
    const float* g1w  = (const float*)d_in[15];
    const float* g1b  = (const float*)d_in[16];
    const float* a21w = (const float*)d_in[17];
    const float* a21b = (const float*)d_in[18];
    const float* a22w = (const float*)d_in[19];
    const float* a22b = (const float*)d_in[20];
    const float* d1w  = (const float*)d_in[21];
    const float* d1b  = (const float*)d_in[22];
    const float* d2w  = (const float*)d_in[23];
    const float* d2b  = (const float*)d_in[24];
    const float* d3w  = (const float*)d_in[25];
    const float* d3b  = (const float*)d_in[26];

    // k2s smem: svis 2048 + uks 4096 + segtot 2048 + SWp 2*257*17*8 + wtmp 256*17*4 = 95,504 B
    const int k2s_smem = 2048 + 4096 + 2048 + 2 * 257 * 17 * 8 + 256 * 17 * 4;
    cudaFuncSetAttribute(k2s, cudaFuncAttributeMaxDynamicSharedMemorySize, k2s_smem);

    k1<<<dim3(8, 16), 256>>>(x, w1a, b1a, w1b, b1b);
    ks<<<dim3(8, 128, 2), 256>>>();
    kz<<<16, 1024>>>();
    k2s<<<dim3(16, 16, 4), 256, k2s_smem>>>(w2a, w2b);
    kr4<<<1024, 256>>>(b2a, b2b);
    k3<<<dim3(8, 64), 256>>>(e2nw);
    k4<<<8, 256>>>(x, e2nb, a11w, a11b, a12w, a12b, g1w, g1b, a21w, a21b,
                   a22w, a22b, d1w, d1b, d2w, d2b, d3w, d3b, (float*)d_out);
}

// round 17
// speedup vs baseline: 1.6840x; 1.0217x over previous
#include <cuda_runtime.h>
#include <math.h>

typedef unsigned long long ull;
typedef unsigned int uint;
#define DV __device__ __forceinline__

// ---------------- scratch (device globals; no allocations) ----------------
__device__ float g_a1[8 * 128 * 256];
__device__ float g_b1[8 * 128 * 256];
__device__ float g_a2[8 * 256 * 256];
__device__ float g_b2[8 * 256 * 256];
__device__ float g_np[8 * 256 * 8];
__device__ float2 g_svi[2][8 * 128 * 256];  // [mode][(b*128+c)*256+k] = {sorted v, idx bits}
__device__ float2 g_uk[2][8 * 128 * 256];   // [mode][(b*128+c)*256+i] = {u, k bits}
__device__ float g_part[4][16][65536];      // c-split partials

DV float lrelu(float x) { return x > 0.f ? x : 0.33f * x; }
DV ull ffma2(ull a, ull b, ull c) {
    ull d; asm("fma.rn.f32x2 %0,%1,%2,%3;" : "=l"(d) : "l"(a), "l"(b), "l"(c)); return d;
}
DV ull pack2(float x, float y) {
    ull d; asm("mov.b64 %0,{%1,%2};" : "=l"(d) : "r"(__float_as_uint(x)), "r"(__float_as_uint(y))); return d;
}
DV float2 unpk(ull v) {
    float2 f; asm("mov.b64 {%0,%1},%2;" : "=f"(f.x), "=f"(f.y) : "l"(v)); return f;
}

// ---------------- k1: layer-1 rank terms (8-c tile) ----------------
__global__ void __launch_bounds__(256) k1(const float* __restrict__ x,
                                          const float* __restrict__ w1a, const float* __restrict__ b1a,
                                          const float* __restrict__ w1b, const float* __restrict__ b1b) {
    __shared__ float wa[8][256], wb[8][256];
    int b = blockIdx.x, c0 = blockIdx.y * 8, t = threadIdx.x;
#pragma unroll
    for (int cc = 0; cc < 8; cc++) {
        wa[cc][t] = w1a[(c0 + cc) * 256 + t];
        wb[cc][t] = w1b[(c0 + cc) * 256 + t];
    }
    __syncthreads();
    const float* xb = x + b * 65536;
    float aA[8], aB[8];
#pragma unroll
    for (int cc = 0; cc < 8; cc++) { aA[cc] = 0.f; aB[cc] = 0.f; }
    const float4* xr = (const float4*)(xb + t * 256);
#pragma unroll 4
    for (int j4 = 0; j4 < 64; j4++) {
        float4 v = xr[j4];
#pragma unroll
        for (int cc = 0; cc < 8; cc++)
            aA[cc] += v.x * wa[cc][j4 * 4] + v.y * wa[cc][j4 * 4 + 1] +
                      v.z * wa[cc][j4 * 4 + 2] + v.w * wa[cc][j4 * 4 + 3];
    }
#pragma unroll 4
    for (int i = 0; i < 256; i++) {
        float xv = xb[i * 256 + t];
#pragma unroll
        for (int cc = 0; cc < 8; cc++) aB[cc] += xv * wb[cc][i];
    }
#pragma unroll
    for (int cc = 0; cc < 8; cc++) {
        g_a1[(b * 128 + c0 + cc) * 256 + t] = aA[cc] + b1a[c0 + cc];
        g_b1[(b * 128 + c0 + cc) * 256 + t] = aB[cc] + b1b[c0 + cc];
    }
}

// ---------------- ks: per-(b,c,mode) bitonic sort + thresholds ----------------
__global__ void __launch_bounds__(256) ks() {
    __shared__ float sv[256];
    __shared__ int si[256];
    int b = blockIdx.x, c = blockIdx.y, t = threadIdx.x;
    int mode = blockIdx.z;
    int base = (b * 128 + c) * 256;
    const float* varr = mode ? g_a1 : g_b1;
    const float* uarr = mode ? g_b1 : g_a1;
    sv[t] = varr[base + t];
    si[t] = t;
    __syncthreads();
    for (int k = 2; k <= 256; k <<= 1) {
        for (int j = k >> 1; j > 0; j >>= 1) {
            int ixj = t ^ j;
            if (ixj > t) {
                bool up = ((t & k) == 0);
                float v0 = sv[t], v1 = sv[ixj];
                if ((v0 > v1) == up) {
                    int i0 = si[t], i1 = si[ixj];
                    sv[t] = v1; sv[ixj] = v0;
                    si[t] = i1; si[ixj] = i0;
                }
            }
            __syncthreads();
        }
    }
    g_svi[mode][base + t] = make_float2(sv[t], __int_as_float(si[t]));
    float u = uarr[base + t];
    float nu = -u;
    int lo = 0, hi = 256;
#pragma unroll
    for (int it = 0; it < 8; it++) {
        int mid = (lo + hi) >> 1;
        if (sv[mid] <= nu) lo = mid + 1; else hi = mid;
    }
    g_uk[mode][base + t] = make_float2(u, __int_as_float(lo));
}

// ---------------- kz: zero the e2n accumulator ----------------
__global__ void kz() { g_np[blockIdx.x * 1024 + threadIdx.x] = 0.f; }

// ---------------- k2s: suffix-sum layer-2; pipelined, double-buffered, c-split x4 ----------------
__global__ void __launch_bounds__(256, 2) k2s(const float* __restrict__ w2a,
                                              const float* __restrict__ w2b) {
    extern __shared__ char smem_raw[];
    float2* svis = (float2*)smem_raw;            // [256]      (16B-aligned rows)
    float2* uks = svis + 256;                    // [2][256]   double-buffered
    float2* segtot = uks + 512;                  // [16][16]
    float2* SWp = segtot + 256;                  // [2][257*17] double-buffered suffix pairs
    float* wtmp = (float*)(SWp + 2 * 257 * 17);  // [256][17]

    int t = threadIdx.x;
    int p0 = blockIdx.x * 16;
    int bm = blockIdx.y, b = bm >> 1, mode = bm & 1;
    int slice = blockIdx.z;
    int c0 = slice * 32;
    const float* W = mode ? w2b : w2a;
    const float2* gsvi = g_svi[mode] + b * 32768;
    const float2* guk = g_uk[mode] + b * 32768;

    int p = t & 15, seg = t >> 4;       // 16 segs x 16 k
    int wlp = t >> 4, wls = t & 15;     // W loader: 16 p rows x 16 k-groups

    if (t < 16) {                        // ki=256 -> empty suffix, both buffers
        SWp[256 * 17 + t] = make_float2(0.f, 0.f);
        SWp[257 * 17 + 256 * 17 + t] = make_float2(0.f, 0.f);
    }

    float acc[16];
#pragma unroll
    for (int m = 0; m < 16; m++) acc[m] = 0.f;

    const float* wbase = W + (size_t)(p0 + wlp) * 32768;

    // ---- prologue: stage + scan c=c0 into buffer 0
    {
        float2 psv = gsvi[c0 * 256 + t];
        float2 puk = guk[c0 * 256 + t];
        svis[t] = psv;
        uks[t] = puk;
        const float* wrow = wbase + c0 * 256;
#pragma unroll
        for (int m = 0; m < 4; m++) {
            float4 f = *(const float4*)(wrow + m * 64 + wls * 4);
            int kb = m * 64 + wls * 4;
            wtmp[(kb + 0) * 17 + wlp] = f.x;
            wtmp[(kb + 1) * 17 + wlp] = f.y;
            wtmp[(kb + 2) * 17 + wlp] = f.z;
            wtmp[(kb + 3) * 17 + wlp] = f.w;
        }
    }
    __syncthreads();
    {
        float sv[16], wv[16];
        const float4* svrow = (const float4*)&svis[seg * 16];
#pragma unroll
        for (int j = 0; j < 8; j++) {
            float4 f4 = svrow[j];
            sv[2 * j] = f4.x;
            wv[2 * j] = wtmp[__float_as_int(f4.y) * 17 + p];
            sv[2 * j + 1] = f4.z;
            wv[2 * j + 1] = wtmp[__float_as_int(f4.w) * 17 + p];
        }
        float sumw = 0.f, sumv = 0.f;
#pragma unroll
        for (int e = 15; e >= 0; e--) {
            sumw += wv[e];
            sumv = fmaf(wv[e], sv[e], sumv);
        }
        segtot[seg * 16 + p] = make_float2(sumw, sumv);
        __syncthreads();
        float runw = 0.f, runv = 0.f;
        for (int s2 = seg + 1; s2 < 16; s2++) {
            float2 st = segtot[s2 * 16 + p];
            runw += st.x; runv += st.y;
        }
#pragma unroll
        for (int e = 15; e >= 0; e--) {
            runw += wv[e];
            runv = fmaf(wv[e], sv[e], runv);
            SWp[(seg * 16 + e) * 17 + p] = make_float2(runw, runv);
        }
    }
    __syncthreads();

    float2 pf_sv, pf_uk;
    float4 pf_w[4];
    for (int cc = 0; cc < 32; cc++) {
        int c = c0 + cc;
        int cur = cc & 1, nxt = cur ^ 1;
        // prefetch c+1 (LDG latency hidden under main)
        if (cc < 31) {
            const float* wrow = wbase + (c + 1) * 256;
            pf_sv = gsvi[(c + 1) * 256 + t];
            pf_uk = guk[(c + 1) * 256 + t];
#pragma unroll
            for (int m = 0; m < 4; m++)
                pf_w[m] = *(const float4*)(wrow + m * 64 + wls * 4);
        }
        // main(c): reads SWp[cur], uks[cur]
        {
            const float2* SW = SWp + cur * (257 * 17);
            float2 sw0 = SW[p];
            const float4* ukrow = (const float4*)&uks[cur * 256 + seg * 16];
#pragma unroll
            for (int mm = 0; mm < 8; mm++) {
                float4 uu = ukrow[mm];
                {
                    int ki = __float_as_int(uu.y);
                    float2 sK = SW[ki * 17 + p];
                    float t1 = fmaf(uu.x, sK.x, sK.y);
                    float t0 = fmaf(uu.x, sw0.x, sw0.y);
                    acc[2 * mm] = fmaf(0.33f, t0, fmaf(1.0f - 0.33f, t1, acc[2 * mm]));
                }
                {
                    int ki = __float_as_int(uu.w);
                    float2 sK = SW[ki * 17 + p];
                    float t1 = fmaf(uu.z, sK.x, sK.y);
                    float t0 = fmaf(uu.z, sw0.x, sw0.y);
                    acc[2 * mm + 1] = fmaf(0.33f, t0, fmaf(1.0f - 0.33f, t1, acc[2 * mm + 1]));
                }
            }
        }
        // stage + scan c+1 into the other buffer
        if (cc < 31) {
            svis[t] = pf_sv;
            uks[nxt * 256 + t] = pf_uk;
#pragma unroll
            for (int m = 0; m < 4; m++) {
                int kb = m * 64 + wls * 4;
                wtmp[(kb + 0) * 17 + wlp] = pf_w[m].x;
                wtmp[(kb + 1) * 17 + wlp] = pf_w[m].y;
                wtmp[(kb + 2) * 17 + wlp] = pf_w[m].z;
                wtmp[(kb + 3) * 17 + wlp] = pf_w[m].w;
            }
            __syncthreads();   // A: staging visible
            float2* SWb = SWp + nxt * (257 * 17);
            float sv[16], wv[16];
            const float4* svrow = (const float4*)&svis[seg * 16];
#pragma unroll
            for (int j = 0; j < 8; j++) {
                float4 f4 = svrow[j];
                sv[2 * j] = f4.x;
                wv[2 * j] = wtmp[__float_as_int(f4.y) * 17 + p];
                sv[2 * j + 1] = f4.z;
                wv[2 * j + 1] = wtmp[__float_as_int(f4.w) * 17 + p];
            }
            float sumw = 0.f, sumv = 0.f;
#pragma unroll
            for (int e = 15; e >= 0; e--) {
                sumw += wv[e];
                sumv = fmaf(wv[e], sv[e], sumv);
            }
            segtot[seg * 16 + p] = make_float2(sumw, sumv);
            __syncthreads();   // B
            float runw = 0.f, runv = 0.f;
            for (int s2 = seg + 1; s2 < 16; s2++) {
                float2 st = segtot[s2 * 16 + p];
                runw += st.x; runv += st.y;
            }
#pragma unroll
            for (int e = 15; e >= 0; e--) {
                runw += wv[e];
                runv = fmaf(wv[e], sv[e], runv);
                SWb[(seg * 16 + e) * 17 + p] = make_float2(runw, runv);
            }
            __syncthreads();   // C: SWp[nxt] ready for main(c+1)
        }
    }
    // epilogue: partial write (no bias; reduced in kr4)
    float* dst = &g_part[slice][bm][0] + (size_t)(p0 + p) * 256 + seg * 16;
#pragma unroll
    for (int m = 0; m < 16; m += 4) {
        float4 o = make_float4(acc[m], acc[m + 1], acc[m + 2], acc[m + 3]);
        *(float4*)(dst + m) = o;
    }
}

// ---------------- kr4: deterministic 4-slice reduction + bias ----------------
__global__ void __launch_bounds__(256) kr4(const float* __restrict__ b2a,
                                           const float* __restrict__ b2b) {
    int idx = (blockIdx.x * 256 + threadIdx.x) * 4;
    int bm = idx >> 16, rem = idx & 65535;
    int p = rem >> 8;
    float4 s = *(const float4*)&g_part[0][bm][rem];
#pragma unroll
    for (int sl = 1; sl < 4; sl++) {
        float4 u = *(const float4*)&g_part[sl][bm][rem];
        s.x += u.x; s.y += u.y; s.z += u.z; s.w += u.w;
    }
    float bias = (bm & 1) ? b2b[p] : b2a[p];
    s.x += bias; s.y += bias; s.z += bias; s.w += bias;
    float* out = ((bm & 1) ? g_b2 : g_a2) + (bm >> 1) * 65536 + rem;
    *(float4*)out = s;
}

// ---------------- k3: e2n contraction (1024 CTAs: 2 channels each) ----------------
__global__ void __launch_bounds__(256) k3(const float* __restrict__ ew) {
    __shared__ float Bsm[256];
    __shared__ ull Esm[256 * 4];
    int b = blockIdx.x, pc = blockIdx.y, tid = threadIdx.x;
    ull a4[4] = {0ULL, 0ULL, 0ULL, 0ULL};
    for (int p = pc * 2; p < pc * 2 + 2; p++) {
        __syncthreads();
        Bsm[tid] = g_b2[(b * 256 + p) * 256 + tid];
        float e[8];
#pragma unroll
        for (int q = 0; q < 8; q++) e[q] = ew[q * 65536 + p * 256 + tid];
#pragma unroll
        for (int q = 0; q < 4; q++) Esm[tid * 4 + q] = pack2(e[2 * q], e[2 * q + 1]);
        __syncthreads();
        float ai = g_a2[(b * 256 + p) * 256 + tid];
#pragma unroll 4
        for (int j = 0; j < 256; j++) {
            float t = lrelu(ai + Bsm[j]);
            ull ts = pack2(t, t);
            const ull* er = &Esm[j * 4];
            a4[0] = ffma2(er[0], ts, a4[0]);
            a4[1] = ffma2(er[1], ts, a4[1]);
            a4[2] = ffma2(er[2], ts, a4[2]);
            a4[3] = ffma2(er[3], ts, a4[3]);
        }
    }
    float* dst = &g_np[b * 2048 + tid * 8];
#pragma unroll
    for (int q = 0; q < 4; q++) {
        float2 f = unpk(a4[q]);
        atomicAdd(dst + 2 * q, f.x);
        atomicAdd(dst + 2 * q + 1, f.y);
    }
}

// ---------------- k4: GCN / pooling / readout / MLP tail ----------------
__global__ void __launch_bounds__(256) k4(const float* __restrict__ x, const float* __restrict__ e2n_b,
    const float* __restrict__ a11_w, const float* __restrict__ a11_b,
    const float* __restrict__ a12_w, const float* __restrict__ a12_b,
    const float* __restrict__ g1_w,  const float* __restrict__ g1_b,
    const float* __restrict__ a21_w, const float* __restrict__ a21_b,
    const float* __restrict__ a22_w, const float* __restrict__ a22_b,
    const float* __restrict__ d1_w,  const float* __restrict__ d1_b,
    const float* __restrict__ d2_w,  const float* __restrict__ d2_b,
    const float* __restrict__ d3_w,  const float* __restrict__ d3_b,
    float* __restrict__ out) {
    __shared__ uint  m0[256][8];
    __shared__ float nod[256][8];
    __shared__ float dg0[256];
    __shared__ float tp[256];
    __shared__ float sc[256];
    __shared__ float t8[256][8];
    __shared__ int   sel[128];
    __shared__ float hg[128][8];
    __shared__ float on[128][8];
    __shared__ uint  m1[128][4];
    __shared__ float dg1[128];
    __shared__ float z[16];
    __shared__ float z1[128];
    __shared__ float z2[64];

    int b = blockIdx.x, t = threadIdx.x;
    const float* xb = x + b * 65536;
    {
        int w = t >> 5, l = t & 31;
        for (int r = 0; r < 32; r++) {
            int i = w * 32 + r;
            int d = 0;
#pragma unroll
            for (int w8 = 0; w8 < 8; w8++) {
                float xv = xb[i * 256 + w8 * 32 + l];
                uint u = __ballot_sync(0xffffffffu, xv > 0.f);
                if (l == 0) { m0[i][w8] = u; d += __popc(u); }
            }
            if (l == 0) dg0[i] = (float)d;
        }
#pragma unroll
        for (int f = 0; f < 8; f++) nod[t][f] = lrelu(g_np[b * 2048 + t * 8 + f] + e2n_b[f]);
    }
    __syncthreads();
    {
        float s = 0;
#pragma unroll
        for (int f = 0; f < 8; f++) s += nod[t][f] * a11_w[f];
        tp[t] = s / dg0[t];
    }
    __syncthreads();
    {
        float s = 0;
        for (int j = 0; j < 256; j++) if ((m0[t][j >> 5] >> (j & 31)) & 1) s += tp[j];
        sc[t] = lrelu(s + a11_b[0]);
    }
    __syncthreads();
    tp[t] = sc[t] * a12_w[0] / dg0[t];
    __syncthreads();
    {
        float s = 0;
        for (int j = 0; j < 256; j++) if ((m0[t][j >> 5] >> (j & 31)) & 1) s += tp[j];
        sc[t] = 1.f / (1.f + expf(-(s + a12_b[0])));
    }
    __syncthreads();
    {
        float my = sc[t]; int r = 0;
        for (int j = 0; j < 256; j++) {
            float vj = sc[j];
            r += (vj > my) || (vj == my && j < t);
        }
        if (r < 128) sel[r] = t;
    }
    __syncthreads();
    for (int idx = t; idx < 1024; idx += 256) {
        int r = idx >> 3, f = idx & 7; int i = sel[r];
        on[r][f] = nod[i][f] * (1.f + sc[i]);
    }
    if (t < 128) {
        int i = sel[t], d = 0;
#pragma unroll
        for (int w = 0; w < 4; w++) {
            uint u = 0;
            for (int l = 0; l < 32; l++) {
                int j = sel[w * 32 + l];
                u |= ((m0[i][j >> 5] >> (j & 31)) & 1u) << l;
            }
            m1[t][w] = u; d += __popc(u);
        }
        dg1[t] = (float)d;
    }
    __syncthreads();
    if (t < 8) {
        float mx = -1e30f, sm = 0;
        for (int r = 0; r < 128; r++) { float v = on[r][t]; mx = fmaxf(mx, v); sm += v; }
        z[t] = mx; z[8 + t] = sm * (1.f / 128.f);
    }
    __syncthreads();
    for (int idx = t; idx < 1024; idx += 256) {
        int r2 = idx >> 3, fo = idx & 7;
        float s = 0;
#pragma unroll
        for (int f = 0; f < 8; f++) s += on[r2][f] * g1_w[fo * 8 + f];
        t8[r2][fo] = s / dg1[r2];
    }
    __syncthreads();
    for (int idx = t; idx < 1024; idx += 256) {
        int r = idx >> 3, fo = idx & 7;
        float s = 0;
        for (int j = 0; j < 128; j++) if ((m1[r][j >> 5] >> (j & 31)) & 1) s += t8[j][fo];
        hg[r][fo] = s + g1_b[fo];
    }
    __syncthreads();
    if (t < 128) {
        float s = 0;
#pragma unroll
        for (int f = 0; f < 8; f++) s += hg[t][f] * a21_w[f];
        tp[t] = s / dg1[t];
    }
    __syncthreads();
    if (t < 128) {
        float s = 0;
        for (int j = 0; j < 128; j++) if ((m1[t][j >> 5] >> (j & 31)) & 1) s += tp[j];
        sc[t] = lrelu(s + a21_b[0]);
    }
    __syncthreads();
    if (t < 128) tp[t] = sc[t] * a22_w[0] / dg1[t];
    __syncthreads();
    if (t < 128) {
        float s = 0;
        for (int j = 0; j < 128; j++) if ((m1[t][j >> 5] >> (j & 31)) & 1) s += tp[j];
        sc[t] = 1.f / (1.f + expf(-(s + a22_b[0])));
    }
    __syncthreads();
    if (t < 128) {
        float my = sc[t]; int r = 0;
        for (int j = 0; j < 128; j++) {
            float vj = sc[j];
            r += (vj > my) || (vj == my && j < t);
        }
        if (r < 64) sel[r] = t;
    }
    __syncthreads();
    for (int idx = t; idx < 512; idx += 256) {
        int r = idx >> 3, f = idx & 7; int i = sel[r];
        on[r][f] = hg[i][f] * (1.f + sc[i]);
    }
    __syncthreads();
    if (t < 8) {
        float mx = -1e30f, sm = 0;
        for (int r = 0; r < 64; r++) { float v = on[r][t]; mx = fmaxf(mx, v); sm += v; }
        z[t] += mx; z[8 + t] += sm * (1.f / 64.f);
    }
    __syncthreads();
    if (t < 128) {
        float s = d1_b[t];
#pragma unroll
        for (int f = 0; f < 16; f++) s += z[f] * d1_w[t * 16 + f];
        z1[t] = lrelu(s);
    }
    __syncthreads();
    if (t < 64) {
        float s = d2_b[t];
        for (int f = 0; f < 128; f++) s += z1[f] * d2_w[t * 128 + f];
        z2[t] = lrelu(s);
    }
    __syncthreads();
    if (t == 0) {
        float s = d3_b[0];
        for (int f = 0; f < 64; f++) s += z2[f] * d3_w[f];
        out[b] = s;
    }
}

// ---------------- launcher ----------------
extern "C" void kernel_launch(void* const* d_in, const int* in_sizes, int n_in,
                              void* d_out, int out_size) {
    const float* x    = (const float*)d_in[0];
    const float* w1a  = (const float*)d_in[1];
    const float* b1a  = (const float*)d_in[2];
    const float* w1b  = (const float*)d_in[3];
    const float* b1b  = (const float*)d_in[4];
    const float* w2a  = (const float*)d_in[5];
    const float* b2a  = (const float*)d_in[6];
    const float* w2b  = (const float*)d_in[7];
    const float* b2b  = (const float*)d_in[8];
    const float* e2nw = (const float*)d_in[9];
    const float* e2nb = (const float*)d_in[10];
    const float* a11w = (const float*)d_in[11];
    const float* a11b = (const float*)d_in[12];
    const float* a12w = (const float*)d_in[13];
    const float* a12b = (const float*)d_in[14];
    const float* g1w  = (const float*)d_in[15];
    const float* g1b  = (const float*)d_in[16];
    const float* a21w = (const float*)d_in[17];
    const float* a21b = (const float*)d_in[18];
    const float* a22w = (const float*)d_in[19];
    const float* a22b = (const float*)d_in[20];
    const float* d1w  = (const float*)d_in[21];
    const float* d1b  = (const float*)d_in[22];
    const float* d2w  = (const float*)d_in[23];
    const float* d2b  = (const float*)d_in[24];
    const float* d3w  = (const float*)d_in[25];
    const float* d3b  = (const float*)d_in[26];

    // k2s smem: svis 2048 + uks 4096 + segtot 2048 + SWp 2*257*17*8 + wtmp 256*17*4 = 95,504 B
    const int k2s_smem = 2048 + 4096 + 2048 + 2 * 257 * 17 * 8 + 256 * 17 * 4;
    cudaFuncSetAttribute(k2s, cudaFuncAttributeMaxDynamicSharedMemorySize, k2s_smem);

    k1<<<dim3(8, 16), 256>>>(x, w1a, b1a, w1b, b1b);
    ks<<<dim3(8, 128, 2), 256>>>();
    kz<<<16, 1024>>>();
    k2s<<<dim3(16, 16, 4), 256, k2s_smem>>>(w2a, w2b);
    kr4<<<1024, 256>>>(b2a, b2b);
    k3<<<dim3(8, 128), 256>>>(e2nw);
    k4<<<8, 256>>>(x, e2nb, a11w, a11b, a12w, a12b, g1w, g1b, a21w, a21b,
                   a22w, a22b, d1w, d1b, d2w, d2b, d3w, d3b, (float*)d_out);
}